// round 5
// baseline (speedup 1.0000x reference)
#include <cuda_runtime.h>
#include <cuda_fp16.h>
#include <cstdint>

#define NN   50000
#define EE   800000
#define KIN  256
#define FOUT 128
#define NEG_ATT 0.2f
#define NEG_ACT 0.01f
#define BN_EPS  1e-5f
#define NB   196    // ceil(NN / 256)

// Scratch (static device arrays — no allocations allowed)
__device__ __align__(16) float   g_h[(size_t)NN * FOUT];   // projected features fp32
__device__ __align__(16) __half2 g_hh[(size_t)NN * 64];    // fp16 copy for edge gather
__device__ __align__(16) float   g_s[NN * 4];              // a_src per node/head
__device__ __align__(16) float   g_d[NN * 4];              // a_dst per node/head
__device__ __align__(16) float   g_stats[256];             // col sum[128], sumsq[128]
__device__ int g_deg[NN];                                  // in-degree histogram
__device__ int g_off[NN + 1];                              // CSR offsets
__device__ int g_cur[NN];                                  // scatter cursors
__device__ int g_srcs[EE];                                 // CSR: src per slot
__device__ int g_bsum[256];                                // per-block degree sums
__device__ int g_bpre[256];                                // exclusive block prefixes

// ---------------------------------------------------------------------------
// Kernel 1: h = x @ W^T  (64x128 tile, BK=32, 4x8 reg tile). Epilogue writes
// fp32 h AND an fp16 copy used by the edge-gather kernel.
// ---------------------------------------------------------------------------
__global__ __launch_bounds__(256) void gemm_k(const float* __restrict__ x,
                                              const float* __restrict__ W) {
    __shared__ float As[32][68];
    __shared__ float Bs[32][128];
    const int row0 = blockIdx.x * 64;
    const int tid  = threadIdx.x;
    const int tr   = tid >> 4;
    const int tc   = tid & 15;

    float acc[4][8];
#pragma unroll
    for (int i = 0; i < 4; i++)
#pragma unroll
        for (int j = 0; j < 8; j++) acc[i][j] = 0.f;

    for (int k0 = 0; k0 < KIN; k0 += 32) {
#pragma unroll
        for (int i = 0; i < 2; i++) {
            int f = tid * 2 + i;
            int r = f >> 3, kk = (f & 7) << 2;
            int gr = row0 + r;
            float4 v = make_float4(0.f, 0.f, 0.f, 0.f);
            if (gr < NN) v = *(const float4*)(x + (size_t)gr * KIN + k0 + kk);
            As[kk + 0][r] = v.x; As[kk + 1][r] = v.y;
            As[kk + 2][r] = v.z; As[kk + 3][r] = v.w;
        }
#pragma unroll
        for (int i = 0; i < 4; i++) {
            int f = tid * 4 + i;
            int j = f >> 3, kk = (f & 7) << 2;
            float4 v = *(const float4*)(W + (size_t)j * KIN + k0 + kk);
            Bs[kk + 0][j] = v.x; Bs[kk + 1][j] = v.y;
            Bs[kk + 2][j] = v.z; Bs[kk + 3][j] = v.w;
        }
        __syncthreads();
#pragma unroll
        for (int k = 0; k < 32; k++) {
            float4 a  = *(const float4*)&As[k][tr * 4];
            float4 b0 = *(const float4*)&Bs[k][tc * 8];
            float4 b1 = *(const float4*)&Bs[k][tc * 8 + 4];
            float av[4] = {a.x, a.y, a.z, a.w};
            float bv[8] = {b0.x, b0.y, b0.z, b0.w, b1.x, b1.y, b1.z, b1.w};
#pragma unroll
            for (int i = 0; i < 4; i++)
#pragma unroll
                for (int j = 0; j < 8; j++) acc[i][j] += av[i] * bv[j];
        }
        __syncthreads();
    }
#pragma unroll
    for (int i = 0; i < 4; i++) {
        int gr = row0 + tr * 4 + i;
        if (gr < NN) {
            float* p = g_h + (size_t)gr * FOUT + tc * 8;
            *(float4*)(p)     = make_float4(acc[i][0], acc[i][1], acc[i][2], acc[i][3]);
            *(float4*)(p + 4) = make_float4(acc[i][4], acc[i][5], acc[i][6], acc[i][7]);
            __half2 hh[4];
            hh[0] = __floats2half2_rn(acc[i][0], acc[i][1]);
            hh[1] = __floats2half2_rn(acc[i][2], acc[i][3]);
            hh[2] = __floats2half2_rn(acc[i][4], acc[i][5]);
            hh[3] = __floats2half2_rn(acc[i][6], acc[i][7]);
            *(uint4*)(g_hh + (size_t)gr * 64 + tc * 4) = *(uint4*)hh;
        }
    }
}

// ---------------------------------------------------------------------------
// Kernel 2: per-node attention scores. One warp per node. Also zeroes the
// BN stats (block 0) and the degree histogram.
// ---------------------------------------------------------------------------
__global__ __launch_bounds__(256) void node_score_k(const float* __restrict__ att_src,
                                                    const float* __restrict__ att_dst) {
    if (blockIdx.x == 0) g_stats[threadIdx.x] = 0.f;
    int gtid = blockIdx.x * blockDim.x + threadIdx.x;
    if (gtid < NN) g_deg[gtid] = 0;

    int warp = gtid >> 5;
    int lane = threadIdx.x & 31;
    if (warp >= NN) return;
    int head = lane >> 3, sub = lane & 7;

    float4 hv  = *(const float4*)(g_h + (size_t)warp * FOUT + lane * 4);
    float4 as4 = *(const float4*)(att_src + head * 32 + sub * 4);
    float4 ad4 = *(const float4*)(att_dst + head * 32 + sub * 4);
    float ps = hv.x * as4.x + hv.y * as4.y + hv.z * as4.z + hv.w * as4.w;
    float pd = hv.x * ad4.x + hv.y * ad4.y + hv.z * ad4.z + hv.w * ad4.w;
#pragma unroll
    for (int o = 4; o; o >>= 1) {
        ps += __shfl_xor_sync(0xFFFFFFFFu, ps, o);
        pd += __shfl_xor_sync(0xFFFFFFFFu, pd, o);
    }
    if (sub == 0) {
        g_s[warp * 4 + head] = ps;
        g_d[warp * 4 + head] = pd;
    }
}

// ---------------------------------------------------------------------------
// Kernel 3: degree histogram over dst.
// ---------------------------------------------------------------------------
__global__ __launch_bounds__(256) void hist_k(const int* __restrict__ ei) {
    int e = blockIdx.x * blockDim.x + threadIdx.x;
    if (e < EE) atomicAdd(&g_deg[ei[EE + e]], 1);
}

// ---------------------------------------------------------------------------
// Kernel 4a: per-block degree sums (196 blocks x 256).
// ---------------------------------------------------------------------------
__global__ __launch_bounds__(256) void blocksum_k() {
    __shared__ int red[256];
    int t = threadIdx.x;
    int i = blockIdx.x * 256 + t;
    red[t] = (i < NN) ? g_deg[i] : 0;
    __syncthreads();
#pragma unroll
    for (int o = 128; o; o >>= 1) {
        if (t < o) red[t] += red[t + o];
        __syncthreads();
    }
    if (t == 0) g_bsum[blockIdx.x] = red[0];
}

// ---------------------------------------------------------------------------
// Kernel 4b: single-block scan of the 196 block sums -> exclusive prefixes.
// ---------------------------------------------------------------------------
__global__ __launch_bounds__(256) void scanblk_k() {
    __shared__ int sc[256];
    int t = threadIdx.x;
    int v = (t < NB) ? g_bsum[t] : 0;
    sc[t] = v;
    __syncthreads();
#pragma unroll
    for (int o = 1; o < 256; o <<= 1) {
        int u = (t >= o) ? sc[t - o] : 0;
        __syncthreads();
        sc[t] += u;
        __syncthreads();
    }
    g_bpre[t] = sc[t] - v;          // exclusive
    if (t == 0) g_off[NN] = EE;
}

// ---------------------------------------------------------------------------
// Kernel 4c: per-block exclusive scan + global base -> offsets & cursors.
// ---------------------------------------------------------------------------
__global__ __launch_bounds__(256) void offsets_k() {
    __shared__ int sc[256];
    int t = threadIdx.x;
    int i = blockIdx.x * 256 + t;
    int v = (i < NN) ? g_deg[i] : 0;
    sc[t] = v;
    __syncthreads();
#pragma unroll
    for (int o = 1; o < 256; o <<= 1) {
        int u = (t >= o) ? sc[t - o] : 0;
        __syncthreads();
        sc[t] += u;
        __syncthreads();
    }
    int excl = sc[t] - v + g_bpre[blockIdx.x];
    if (i < NN) { g_off[i] = excl; g_cur[i] = excl; }
}

// ---------------------------------------------------------------------------
// Kernel 5: scatter edges into CSR slots.
// ---------------------------------------------------------------------------
__global__ __launch_bounds__(256) void scatter_k(const int* __restrict__ ei) {
    int e = blockIdx.x * blockDim.x + threadIdx.x;
    if (e >= EE) return;
    int dst = ei[EE + e];
    int pos = atomicAdd(&g_cur[dst], 1);
    g_srcs[pos] = ei[e];
}

// ---------------------------------------------------------------------------
// Kernel 6: per-node gather-aggregate. One warp per dst node, 4-way unrolled
// (batched index loads -> batched score loads -> batched gathers) for MLP.
// ---------------------------------------------------------------------------
__global__ __launch_bounds__(256) void agg_k(const float* __restrict__ bias,
                                             float* __restrict__ out) {
    int n = (blockIdx.x * blockDim.x + threadIdx.x) >> 5;
    int lane = threadIdx.x & 31;
    if (n >= NN) return;
    const int head = lane >> 3;

    const float d_n = g_d[n * 4 + head];
    float e0 = g_s[n * 4 + head] + d_n;
    e0 = e0 < 0.f ? NEG_ATT * e0 : e0;
    float w = __expf(e0);

    float4 hs = *(const float4*)(g_h + (size_t)n * FOUT + lane * 4);
    float a0 = w * hs.x, a1 = w * hs.y, a2 = w * hs.z, a3 = w * hs.w;
    float b0 = 0.f, b1 = 0.f, b2 = 0.f, b3 = 0.f;
    float den0 = w, den1 = 0.f;

    const uint2* __restrict__ hh = (const uint2*)g_hh;
    int i = g_off[n];
    const int end = g_off[n + 1];

    for (; i + 4 <= end; i += 4) {
        int s0 = g_srcs[i], s1 = g_srcs[i + 1], s2 = g_srcs[i + 2], s3 = g_srcs[i + 3];
        float sv0 = g_s[s0 * 4 + head];
        float sv1 = g_s[s1 * 4 + head];
        float sv2 = g_s[s2 * 4 + head];
        float sv3 = g_s[s3 * 4 + head];
        uint2 p0 = hh[(size_t)s0 * 32 + lane];
        uint2 p1 = hh[(size_t)s1 * 32 + lane];
        uint2 p2 = hh[(size_t)s2 * 32 + lane];
        uint2 p3 = hh[(size_t)s3 * 32 + lane];
        float ea = sv0 + d_n; ea = ea < 0.f ? NEG_ATT * ea : ea;
        float eb = sv1 + d_n; eb = eb < 0.f ? NEG_ATT * eb : eb;
        float ec = sv2 + d_n; ec = ec < 0.f ? NEG_ATT * ec : ec;
        float ed = sv3 + d_n; ed = ed < 0.f ? NEG_ATT * ed : ed;
        float w0 = __expf(ea), w1 = __expf(eb), w2 = __expf(ec), w3 = __expf(ed);
        den0 += w0 + w1; den1 += w2 + w3;
        float2 l0 = __half22float2(*(__half2*)&p0.x), u0 = __half22float2(*(__half2*)&p0.y);
        float2 l1 = __half22float2(*(__half2*)&p1.x), u1 = __half22float2(*(__half2*)&p1.y);
        float2 l2 = __half22float2(*(__half2*)&p2.x), u2 = __half22float2(*(__half2*)&p2.y);
        float2 l3 = __half22float2(*(__half2*)&p3.x), u3 = __half22float2(*(__half2*)&p3.y);
        a0 = fmaf(w0, l0.x, fmaf(w1, l1.x, a0));
        a1 = fmaf(w0, l0.y, fmaf(w1, l1.y, a1));
        a2 = fmaf(w0, u0.x, fmaf(w1, u1.x, a2));
        a3 = fmaf(w0, u0.y, fmaf(w1, u1.y, a3));
        b0 = fmaf(w2, l2.x, fmaf(w3, l3.x, b0));
        b1 = fmaf(w2, l2.y, fmaf(w3, l3.y, b1));
        b2 = fmaf(w2, u2.x, fmaf(w3, u3.x, b2));
        b3 = fmaf(w2, u2.y, fmaf(w3, u3.y, b3));
    }
    for (; i < end; i++) {
        int s0 = g_srcs[i];
        float sv0 = g_s[s0 * 4 + head];
        uint2 p0 = hh[(size_t)s0 * 32 + lane];
        float ea = sv0 + d_n; ea = ea < 0.f ? NEG_ATT * ea : ea;
        float w0 = __expf(ea);
        den0 += w0;
        float2 l0 = __half22float2(*(__half2*)&p0.x), u0 = __half22float2(*(__half2*)&p0.y);
        a0 = fmaf(w0, l0.x, a0); a1 = fmaf(w0, l0.y, a1);
        a2 = fmaf(w0, u0.x, a2); a3 = fmaf(w0, u0.y, a3);
    }

    float rinv = 1.0f / (den0 + den1);
    float4 b4 = *(const float4*)(bias + lane * 4);
    *(float4*)(out + (size_t)n * FOUT + lane * 4) =
        make_float4(fmaf(a0 + b0, rinv, b4.x), fmaf(a1 + b1, rinv, b4.y),
                    fmaf(a2 + b2, rinv, b4.z), fmaf(a3 + b3, rinv, b4.w));
}

// ---------------------------------------------------------------------------
// Kernel 7: column sum / sumsq of y (already includes bias). float4 per thread.
// ---------------------------------------------------------------------------
__global__ __launch_bounds__(256) void stats_k(const float* __restrict__ out) {
    const int t = threadIdx.x;
    const int cg = t & 31;
    const int rw = t >> 5;
    float s[4] = {0.f, 0.f, 0.f, 0.f}, q[4] = {0.f, 0.f, 0.f, 0.f};
    for (int r = blockIdx.x * 8 + rw; r < NN; r += gridDim.x * 8) {
        float4 v = *(const float4*)(out + (size_t)r * FOUT + cg * 4);
        s[0] += v.x; q[0] = fmaf(v.x, v.x, q[0]);
        s[1] += v.y; q[1] = fmaf(v.y, v.y, q[1]);
        s[2] += v.z; q[2] = fmaf(v.z, v.z, q[2]);
        s[3] += v.w; q[3] = fmaf(v.w, v.w, q[3]);
    }
#pragma unroll
    for (int j = 0; j < 4; j++) {
        atomicAdd(&g_stats[cg * 4 + j], s[j]);
        atomicAdd(&g_stats[128 + cg * 4 + j], q[j]);
    }
}

// ---------------------------------------------------------------------------
// Kernel 8: finalize — BN + LeakyReLU(0.01), float4 in place.
// ---------------------------------------------------------------------------
__global__ __launch_bounds__(256) void final_k(float* __restrict__ out,
                                               const float* __restrict__ gamma,
                                               const float* __restrict__ beta) {
    size_t idx = (size_t)blockIdx.x * blockDim.x + threadIdx.x;   // N*32 quads
    if (idx >= (size_t)NN * 32) return;
    int c = (int)(idx & 31) * 4;
    size_t r = idx >> 5;
    float4 v = *(float4*)(out + r * FOUT + c);
    const float invN = 1.0f / NN;
    float y[4] = {v.x, v.y, v.z, v.w};
#pragma unroll
    for (int j = 0; j < 4; j++) {
        int cc = c + j;
        float mu  = g_stats[cc] * invN;
        float var = fmaf(g_stats[128 + cc], invN, -mu * mu);
        float z = (y[j] - mu) * rsqrtf(var + BN_EPS) * gamma[cc] + beta[cc];
        y[j] = z < 0.f ? NEG_ACT * z : z;
    }
    *(float4*)(out + r * FOUT + c) = make_float4(y[0], y[1], y[2], y[3]);
}

// ---------------------------------------------------------------------------
extern "C" void kernel_launch(void* const* d_in, const int* in_sizes, int n_in,
                              void* d_out, int out_size) {
    const float* x       = (const float*)d_in[0];
    const int*   ei      = (const int*)  d_in[1];
    const float* W       = (const float*)d_in[2];
    const float* att_src = (const float*)d_in[3];
    const float* att_dst = (const float*)d_in[4];
    const float* bias    = (const float*)d_in[5];
    const float* gamma   = (const float*)d_in[6];
    const float* beta    = (const float*)d_in[7];
    float* out = (float*)d_out;

    gemm_k<<<(NN + 63) / 64, 256>>>(x, W);
    node_score_k<<<(NN * 32 + 255) / 256, 256>>>(att_src, att_dst);
    hist_k<<<(EE + 255) / 256, 256>>>(ei);
    blocksum_k<<<NB, 256>>>();
    scanblk_k<<<1, 256>>>();
    offsets_k<<<NB, 256>>>();
    scatter_k<<<(EE + 255) / 256, 256>>>(ei);
    agg_k<<<(NN * 32 + 255) / 256, 256>>>(bias, out);
    stats_k<<<512, 256>>>(out);
    final_k<<<(int)(((size_t)NN * 32 + 255) / 256), 256>>>(out, gamma, beta);
}

// round 6
// speedup vs baseline: 1.5325x; 1.5325x over previous
#include <cuda_runtime.h>
#include <cuda_fp16.h>
#include <cstdint>

#define NN   50000
#define EE   800000
#define KIN  256
#define FOUT 128
#define NEG_ATT 0.2f
#define NEG_ACT 0.01f
#define BN_EPS  1e-5f

// Scratch (static device arrays — no allocations allowed)
__device__ __align__(16) float   g_h[(size_t)NN * FOUT];   // projected features fp32
__device__ __align__(16) __half2 g_hh[(size_t)NN * 64];    // fp16 mirror for edge gather
__device__ __align__(16) float   g_s[NN * 4];              // a_src per node/head
__device__ __align__(16) float   g_d[NN * 4];              // a_dst per node/head
__device__ __align__(16) float   g_den[NN * 4];            // softmax denominator
__device__ __align__(16) float   g_dinv[NN * 4];           // 1 / denominator
__device__ __align__(16) float   g_stats[256];             // col sum[128], sumsq[128]

// ---------------------------------------------------------------------------
// Kernel 1: h = x @ W^T  (64x128 tile, BK=32, 4x8 reg tile). Epilogue writes
// fp32 h AND the fp16 mirror used by the edge kernel.
// ---------------------------------------------------------------------------
__global__ __launch_bounds__(256) void gemm_k(const float* __restrict__ x,
                                              const float* __restrict__ W) {
    __shared__ float As[32][68];
    __shared__ float Bs[32][128];
    const int row0 = blockIdx.x * 64;
    const int tid  = threadIdx.x;
    const int tr   = tid >> 4;
    const int tc   = tid & 15;

    float acc[4][8];
#pragma unroll
    for (int i = 0; i < 4; i++)
#pragma unroll
        for (int j = 0; j < 8; j++) acc[i][j] = 0.f;

    for (int k0 = 0; k0 < KIN; k0 += 32) {
#pragma unroll
        for (int i = 0; i < 2; i++) {
            int f = tid * 2 + i;
            int r = f >> 3, kk = (f & 7) << 2;
            int gr = row0 + r;
            float4 v = make_float4(0.f, 0.f, 0.f, 0.f);
            if (gr < NN) v = *(const float4*)(x + (size_t)gr * KIN + k0 + kk);
            As[kk + 0][r] = v.x; As[kk + 1][r] = v.y;
            As[kk + 2][r] = v.z; As[kk + 3][r] = v.w;
        }
#pragma unroll
        for (int i = 0; i < 4; i++) {
            int f = tid * 4 + i;
            int j = f >> 3, kk = (f & 7) << 2;
            float4 v = *(const float4*)(W + (size_t)j * KIN + k0 + kk);
            Bs[kk + 0][j] = v.x; Bs[kk + 1][j] = v.y;
            Bs[kk + 2][j] = v.z; Bs[kk + 3][j] = v.w;
        }
        __syncthreads();
#pragma unroll
        for (int k = 0; k < 32; k++) {
            float4 a  = *(const float4*)&As[k][tr * 4];
            float4 b0 = *(const float4*)&Bs[k][tc * 8];
            float4 b1 = *(const float4*)&Bs[k][tc * 8 + 4];
            float av[4] = {a.x, a.y, a.z, a.w};
            float bv[8] = {b0.x, b0.y, b0.z, b0.w, b1.x, b1.y, b1.z, b1.w};
#pragma unroll
            for (int i = 0; i < 4; i++)
#pragma unroll
                for (int j = 0; j < 8; j++) acc[i][j] += av[i] * bv[j];
        }
        __syncthreads();
    }
#pragma unroll
    for (int i = 0; i < 4; i++) {
        int gr = row0 + tr * 4 + i;
        if (gr < NN) {
            float* p = g_h + (size_t)gr * FOUT + tc * 8;
            *(float4*)(p)     = make_float4(acc[i][0], acc[i][1], acc[i][2], acc[i][3]);
            *(float4*)(p + 4) = make_float4(acc[i][4], acc[i][5], acc[i][6], acc[i][7]);
            __half2 hh[4];
            hh[0] = __floats2half2_rn(acc[i][0], acc[i][1]);
            hh[1] = __floats2half2_rn(acc[i][2], acc[i][3]);
            hh[2] = __floats2half2_rn(acc[i][4], acc[i][5]);
            hh[3] = __floats2half2_rn(acc[i][6], acc[i][7]);
            *(uint4*)(g_hh + (size_t)gr * 64 + tc * 4) = *(uint4*)hh;
        }
    }
}

// ---------------------------------------------------------------------------
// Kernel 2: per-node attention scores + self-loop init of accumulators.
// One warp per node. Block 0 also zeroes the BN stats accumulators.
// Self-loop contribution uses fp32 h (exact), matching R3 behavior.
// ---------------------------------------------------------------------------
__global__ __launch_bounds__(256) void node_init_k(const float* __restrict__ att_src,
                                                   const float* __restrict__ att_dst,
                                                   float* __restrict__ out) {
    if (blockIdx.x == 0) g_stats[threadIdx.x] = 0.f;

    int warp = (blockIdx.x * blockDim.x + threadIdx.x) >> 5;
    int lane = threadIdx.x & 31;
    if (warp >= NN) return;
    int head = lane >> 3, sub = lane & 7;

    float4 hv  = *(const float4*)(g_h + (size_t)warp * FOUT + lane * 4);
    float4 as4 = *(const float4*)(att_src + head * 32 + sub * 4);
    float4 ad4 = *(const float4*)(att_dst + head * 32 + sub * 4);
    float ps = hv.x * as4.x + hv.y * as4.y + hv.z * as4.z + hv.w * as4.w;
    float pd = hv.x * ad4.x + hv.y * ad4.y + hv.z * ad4.z + hv.w * ad4.w;
#pragma unroll
    for (int o = 4; o; o >>= 1) {
        ps += __shfl_xor_sync(0xFFFFFFFFu, ps, o);
        pd += __shfl_xor_sync(0xFFFFFFFFu, pd, o);
    }
    float e = ps + pd;
    e = e < 0.f ? NEG_ATT * e : e;
    float w = __expf(e);

    *(float4*)(out + (size_t)warp * FOUT + lane * 4) =
        make_float4(w * hv.x, w * hv.y, w * hv.z, w * hv.w);
    if (sub == 0) {
        g_s[warp * 4 + head]   = ps;
        g_d[warp * 4 + head]   = pd;
        g_den[warp * 4 + head] = w;
    }
}

// ---------------------------------------------------------------------------
// Kernel 3: edge scatter. One warp per edge. fp16 gather of h (halves the
// dominant read stream), fp32 RED.128 accumulation.
// ---------------------------------------------------------------------------
__global__ __launch_bounds__(256) void edge_k(const int* __restrict__ ei,
                                              float* __restrict__ out) {
    int warp = (int)((blockIdx.x * (unsigned)blockDim.x + threadIdx.x) >> 5);
    int lane = threadIdx.x & 31;
    if (warp >= EE) return;
    int src = ei[warp];
    int dst = ei[EE + warp];
    int head = lane >> 3;

    float e = g_s[src * 4 + head] + g_d[dst * 4 + head];
    e = e < 0.f ? NEG_ATT * e : e;
    float w = __expf(e);
    if ((lane & 7) == 0)
        atomicAdd(&g_den[dst * 4 + head], w);

    uint2 p = *(const uint2*)((const uint2*)g_hh + (size_t)src * 32 + lane);
    float2 lo = __half22float2(*(__half2*)&p.x);
    float2 hi = __half22float2(*(__half2*)&p.y);
    float* q = out + (size_t)dst * FOUT + lane * 4;
    asm volatile("red.global.add.v4.f32 [%0], {%1,%2,%3,%4};"
                 :: "l"(q), "f"(w * lo.x), "f"(w * lo.y),
                    "f"(w * hi.x), "f"(w * hi.y)
                 : "memory");
}

// ---------------------------------------------------------------------------
// Kernel 3b: reciprocal of the softmax denominator.
// ---------------------------------------------------------------------------
__global__ __launch_bounds__(256) void inv_k() {
    int i = blockIdx.x * blockDim.x + threadIdx.x;
    if (i < NN * 4) g_dinv[i] = 1.0f / g_den[i];
}

// ---------------------------------------------------------------------------
// Kernel 4: column-wise sum / sumsq of y = out*dinv + bias.
// Row-strided blocks (coalesced rows), unroll-4 for MLP.
// ---------------------------------------------------------------------------
__global__ __launch_bounds__(128) void stats_k(const float* __restrict__ out,
                                               const float* __restrict__ bias) {
    const int c = threadIdx.x;
    const float b = bias[c];
    const int hsel = c >> 5;
    float s0 = 0.f, s1 = 0.f, q0 = 0.f, q1 = 0.f;

    int r = blockIdx.x;
    const int stride = gridDim.x;
    for (; r + 3 * stride < NN; r += 4 * stride) {
        float y0 = fmaf(out[(size_t)(r)              * FOUT + c], g_dinv[(r)              * 4 + hsel], b);
        float y1 = fmaf(out[(size_t)(r + stride)     * FOUT + c], g_dinv[(r + stride)     * 4 + hsel], b);
        float y2 = fmaf(out[(size_t)(r + 2 * stride) * FOUT + c], g_dinv[(r + 2 * stride) * 4 + hsel], b);
        float y3 = fmaf(out[(size_t)(r + 3 * stride) * FOUT + c], g_dinv[(r + 3 * stride) * 4 + hsel], b);
        s0 += y0 + y1; s1 += y2 + y3;
        q0 = fmaf(y0, y0, fmaf(y1, y1, q0));
        q1 = fmaf(y2, y2, fmaf(y3, y3, q1));
    }
    for (; r < NN; r += stride) {
        float y = fmaf(out[(size_t)r * FOUT + c], g_dinv[r * 4 + hsel], b);
        s0 += y; q0 = fmaf(y, y, q0);
    }
    atomicAdd(&g_stats[c], s0 + s1);
    atomicAdd(&g_stats[128 + c], q0 + q1);
}

// ---------------------------------------------------------------------------
// Kernel 5: finalize — normalize, BN affine, LeakyReLU(0.01), float4 in place.
// ---------------------------------------------------------------------------
__global__ __launch_bounds__(256) void final_k(float* __restrict__ out,
                                               const float* __restrict__ bias,
                                               const float* __restrict__ gamma,
                                               const float* __restrict__ beta) {
    size_t idx = (size_t)blockIdx.x * blockDim.x + threadIdx.x;     // over N*32
    if (idx >= (size_t)NN * 32) return;
    int cq = (int)(idx & 31);
    size_t r = idx >> 5;
    int c = cq * 4;
    float di = g_dinv[r * 4 + (c >> 5)];

    float4 v = *(float4*)(out + r * FOUT + c);
    const float invN = 1.0f / NN;
    float y[4] = {v.x, v.y, v.z, v.w};
#pragma unroll
    for (int j = 0; j < 4; j++) {
        int cc = c + j;
        float yy = fmaf(y[j], di, bias[cc]);
        float mu  = g_stats[cc] * invN;
        float var = fmaf(g_stats[128 + cc], invN, -mu * mu);
        float z = (yy - mu) * rsqrtf(var + BN_EPS) * gamma[cc] + beta[cc];
        y[j] = z < 0.f ? NEG_ACT * z : z;
    }
    *(float4*)(out + r * FOUT + c) = make_float4(y[0], y[1], y[2], y[3]);
}

// ---------------------------------------------------------------------------
extern "C" void kernel_launch(void* const* d_in, const int* in_sizes, int n_in,
                              void* d_out, int out_size) {
    const float* x       = (const float*)d_in[0];
    const int*   ei      = (const int*)  d_in[1];
    const float* W       = (const float*)d_in[2];
    const float* att_src = (const float*)d_in[3];
    const float* att_dst = (const float*)d_in[4];
    const float* bias    = (const float*)d_in[5];
    const float* gamma   = (const float*)d_in[6];
    const float* beta    = (const float*)d_in[7];
    float* out = (float*)d_out;

    gemm_k<<<(NN + 63) / 64, 256>>>(x, W);
    node_init_k<<<(NN * 32 + 255) / 256, 256>>>(att_src, att_dst, out);
    edge_k<<<(EE * 32 + 255) / 256, 256>>>(ei, out);
    inv_k<<<(NN * 4 + 255) / 256, 256>>>();
    stats_k<<<2048, 128>>>(out, bias);
    final_k<<<(int)(((size_t)NN * 32 + 255) / 256), 256>>>(out, bias, gamma, beta);
}

// round 7
// speedup vs baseline: 1.8744x; 1.2231x over previous
#include <cuda_runtime.h>
#include <cuda_fp16.h>
#include <cstdint>

#define NN   50000
#define EE   800000
#define KIN  256
#define FOUT 128
#define NEG_ATT 0.2f
#define NEG_ACT 0.01f
#define BN_EPS  1e-5f

// Scratch (static device arrays — no allocations allowed)
__device__ __align__(16) float   g_h[(size_t)NN * FOUT];   // projected features fp32
__device__ __align__(16) __half2 g_hh[(size_t)NN * 64];    // fp16 mirror for edge gather
__device__ __align__(16) float   g_s[NN * 4];              // a_src per node/head
__device__ __align__(16) float   g_d[NN * 4];              // a_dst per node/head
__device__ __align__(16) float   g_den[NN * 4];            // softmax denominator
__device__ __align__(16) float   g_dinv[NN * 4];           // 1 / denominator
__device__ __align__(16) float   g_stats[256];             // col sum[128], sumsq[128]

// ---------------------------------------------------------------------------
// Kernel 1: h = x @ W^T via 3xTF32 mma.m16n8k8 (fp32-grade accuracy).
// Block 128x128, BK=16. Smem layout: per row, 8 pairs of 16B chunks
// [hi_k, hi_{k+4}, lo_k, lo_{k+4}] with 192B row stride -> every fragment
// read is ONE conflict-free LDS.128. 12 LDS.128 + 48 HMMA per warp per
// 8-k step. LDG for the next tile issued before the MMA block.
// ---------------------------------------------------------------------------
__device__ __forceinline__ uint32_t f2tf(float f) {
    uint32_t r; asm("cvt.rna.tf32.f32 %0, %1;" : "=r"(r) : "f"(f)); return r;
}

#define MMA_TF32(D, A0, A1, A2, A3, B0, B1)                                \
    asm volatile("mma.sync.aligned.m16n8k8.row.col.f32.tf32.tf32.f32 "     \
                 "{%0,%1,%2,%3},{%4,%5,%6,%7},{%8,%9},{%0,%1,%2,%3};"      \
                 : "+f"(D[0]), "+f"(D[1]), "+f"(D[2]), "+f"(D[3])          \
                 : "r"(A0), "r"(A1), "r"(A2), "r"(A3), "r"(B0), "r"(B1))

#define RS 48   // uints per smem row (192 bytes)

__global__ __launch_bounds__(256, 2) void gemm_tc(const float* __restrict__ x,
                                                  const float* __restrict__ W) {
    __shared__ __align__(16) uint32_t As[128 * RS];
    __shared__ __align__(16) uint32_t Bs[128 * RS];

    const int tid  = threadIdx.x;
    const int wid  = tid >> 5, lane = tid & 31;
    const int wm   = wid >> 1, wn = wid & 1;     // warp grid 4x2 (M x N)
    const int g    = lane >> 2, t = lane & 3;
    const int row0 = blockIdx.x * 128;

    // staging: thread handles half a row (8 consecutive k)
    const int sr   = tid >> 1;       // 0..127
    const int sh   = tid & 1;        // k half: 0 or 8
    const int arow = row0 + sr;
    const bool aval = arow < NN;

    float va[8], vb[8];
    float acc[2][8][4];
#pragma unroll
    for (int mt = 0; mt < 2; mt++)
#pragma unroll
        for (int nt = 0; nt < 8; nt++)
#pragma unroll
            for (int i = 0; i < 4; i++) acc[mt][nt][i] = 0.f;

    // prologue load (k0 = 0)
    {
        float4 a0 = make_float4(0.f,0.f,0.f,0.f), a1 = a0;
        if (aval) {
            a0 = *(const float4*)(x + (size_t)arow * KIN + sh * 8);
            a1 = *(const float4*)(x + (size_t)arow * KIN + sh * 8 + 4);
        }
        float4 b0 = *(const float4*)(W + (size_t)sr * KIN + sh * 8);
        float4 b1 = *(const float4*)(W + (size_t)sr * KIN + sh * 8 + 4);
        va[0]=a0.x; va[1]=a0.y; va[2]=a0.z; va[3]=a0.w;
        va[4]=a1.x; va[5]=a1.y; va[6]=a1.z; va[7]=a1.w;
        vb[0]=b0.x; vb[1]=b0.y; vb[2]=b0.z; vb[3]=b0.w;
        vb[4]=b1.x; vb[5]=b1.y; vb[6]=b1.z; vb[7]=b1.w;
    }

    uint32_t* Ap = As + sr * RS + sh * 16;
    uint32_t* Bp = Bs + sr * RS + sh * 16;

    for (int it = 0; it < 16; it++) {
        __syncthreads();          // previous MMA done reading smem
        // convert + store: 4 STS.128 per matrix
#pragma unroll
        for (int p = 0; p < 4; p++) {
            uint32_t h0 = f2tf(va[p]), h1 = f2tf(va[p + 4]);
            uint32_t l0 = f2tf(va[p] - __uint_as_float(h0));
            uint32_t l1 = f2tf(va[p + 4] - __uint_as_float(h1));
            *(uint4*)(Ap + p * 4) = make_uint4(h0, h1, l0, l1);
            h0 = f2tf(vb[p]); h1 = f2tf(vb[p + 4]);
            l0 = f2tf(vb[p] - __uint_as_float(h0));
            l1 = f2tf(vb[p + 4] - __uint_as_float(h1));
            *(uint4*)(Bp + p * 4) = make_uint4(h0, h1, l0, l1);
        }
        __syncthreads();

        // issue global loads for the NEXT tile (latency hidden under MMA)
        if (it < 15) {
            int k0 = (it + 1) * 16;
            float4 a0 = make_float4(0.f,0.f,0.f,0.f), a1 = a0;
            if (aval) {
                a0 = *(const float4*)(x + (size_t)arow * KIN + k0 + sh * 8);
                a1 = *(const float4*)(x + (size_t)arow * KIN + k0 + sh * 8 + 4);
            }
            float4 b0 = *(const float4*)(W + (size_t)sr * KIN + k0 + sh * 8);
            float4 b1 = *(const float4*)(W + (size_t)sr * KIN + k0 + sh * 8 + 4);
            va[0]=a0.x; va[1]=a0.y; va[2]=a0.z; va[3]=a0.w;
            va[4]=a1.x; va[5]=a1.y; va[6]=a1.z; va[7]=a1.w;
            vb[0]=b0.x; vb[1]=b0.y; vb[2]=b0.z; vb[3]=b0.w;
            vb[4]=b1.x; vb[5]=b1.y; vb[6]=b1.z; vb[7]=b1.w;
        }

        // MMA over the two 8-k steps of this 16-k tile
#pragma unroll
        for (int blk = 0; blk < 2; blk++) {
            uint32_t ah[2][4], al[2][4];
#pragma unroll
            for (int mt = 0; mt < 2; mt++) {
                int r = wm * 32 + mt * 16 + g;
                uint4 u = *(const uint4*)(As + r * RS + blk * 16 + t * 4);
                uint4 v = *(const uint4*)(As + (r + 8) * RS + blk * 16 + t * 4);
                ah[mt][0] = u.x; ah[mt][1] = v.x; ah[mt][2] = u.y; ah[mt][3] = v.y;
                al[mt][0] = u.z; al[mt][1] = v.z; al[mt][2] = u.w; al[mt][3] = v.w;
            }
#pragma unroll
            for (int nt = 0; nt < 8; nt++) {
                int c = wn * 64 + nt * 8 + g;
                uint4 v = *(const uint4*)(Bs + c * RS + blk * 16 + t * 4);
#pragma unroll
                for (int mt = 0; mt < 2; mt++) {
                    MMA_TF32(acc[mt][nt], ah[mt][0], ah[mt][1], ah[mt][2], ah[mt][3], v.x, v.y);
                    MMA_TF32(acc[mt][nt], ah[mt][0], ah[mt][1], ah[mt][2], ah[mt][3], v.z, v.w);
                    MMA_TF32(acc[mt][nt], al[mt][0], al[mt][1], al[mt][2], al[mt][3], v.x, v.y);
                }
            }
        }
    }

    // Epilogue: c0/c1 -> (row g, cols 2t,2t+1); c2/c3 -> row g+8. Also fp16 mirror.
#pragma unroll
    for (int mt = 0; mt < 2; mt++) {
        int r = row0 + wm * 32 + mt * 16 + g;
#pragma unroll
        for (int nt = 0; nt < 8; nt++) {
            int col = wn * 64 + nt * 8 + 2 * t;
            if (r < NN) {
                *(float2*)(g_h + (size_t)r * FOUT + col) =
                    make_float2(acc[mt][nt][0], acc[mt][nt][1]);
                g_hh[(size_t)r * 64 + (col >> 1)] =
                    __floats2half2_rn(acc[mt][nt][0], acc[mt][nt][1]);
            }
            if (r + 8 < NN) {
                *(float2*)(g_h + (size_t)(r + 8) * FOUT + col) =
                    make_float2(acc[mt][nt][2], acc[mt][nt][3]);
                g_hh[(size_t)(r + 8) * 64 + (col >> 1)] =
                    __floats2half2_rn(acc[mt][nt][2], acc[mt][nt][3]);
            }
        }
    }
}

// ---------------------------------------------------------------------------
// Kernel 2: per-node attention scores + self-loop init of accumulators.
// One warp per node. Block 0 also zeroes the BN stats accumulators.
// ---------------------------------------------------------------------------
__global__ __launch_bounds__(256) void node_init_k(const float* __restrict__ att_src,
                                                   const float* __restrict__ att_dst,
                                                   float* __restrict__ out) {
    if (blockIdx.x == 0) g_stats[threadIdx.x] = 0.f;

    int warp = (blockIdx.x * blockDim.x + threadIdx.x) >> 5;
    int lane = threadIdx.x & 31;
    if (warp >= NN) return;
    int head = lane >> 3, sub = lane & 7;

    float4 hv  = *(const float4*)(g_h + (size_t)warp * FOUT + lane * 4);
    float4 as4 = *(const float4*)(att_src + head * 32 + sub * 4);
    float4 ad4 = *(const float4*)(att_dst + head * 32 + sub * 4);
    float ps = hv.x * as4.x + hv.y * as4.y + hv.z * as4.z + hv.w * as4.w;
    float pd = hv.x * ad4.x + hv.y * ad4.y + hv.z * ad4.z + hv.w * ad4.w;
#pragma unroll
    for (int o = 4; o; o >>= 1) {
        ps += __shfl_xor_sync(0xFFFFFFFFu, ps, o);
        pd += __shfl_xor_sync(0xFFFFFFFFu, pd, o);
    }
    float e = ps + pd;
    e = e < 0.f ? NEG_ATT * e : e;
    float w = __expf(e);

    *(float4*)(out + (size_t)warp * FOUT + lane * 4) =
        make_float4(w * hv.x, w * hv.y, w * hv.z, w * hv.w);
    if (sub == 0) {
        g_s[warp * 4 + head]   = ps;
        g_d[warp * 4 + head]   = pd;
        g_den[warp * 4 + head] = w;
    }
}

// ---------------------------------------------------------------------------
// Kernel 3: edge scatter. One warp per edge. fp16 gather of h, fp32 RED.128.
// ---------------------------------------------------------------------------
__global__ __launch_bounds__(256) void edge_k(const int* __restrict__ ei,
                                              float* __restrict__ out) {
    int warp = (int)((blockIdx.x * (unsigned)blockDim.x + threadIdx.x) >> 5);
    int lane = threadIdx.x & 31;
    if (warp >= EE) return;
    int src = ei[warp];
    int dst = ei[EE + warp];
    int head = lane >> 3;

    float e = g_s[src * 4 + head] + g_d[dst * 4 + head];
    e = e < 0.f ? NEG_ATT * e : e;
    float w = __expf(e);
    if ((lane & 7) == 0)
        atomicAdd(&g_den[dst * 4 + head], w);

    uint2 p = *(const uint2*)((const uint2*)g_hh + (size_t)src * 32 + lane);
    float2 lo = __half22float2(*(__half2*)&p.x);
    float2 hi = __half22float2(*(__half2*)&p.y);
    float* q = out + (size_t)dst * FOUT + lane * 4;
    asm volatile("red.global.add.v4.f32 [%0], {%1,%2,%3,%4};"
                 :: "l"(q), "f"(w * lo.x), "f"(w * lo.y),
                    "f"(w * hi.x), "f"(w * hi.y)
                 : "memory");
}

// ---------------------------------------------------------------------------
// Kernel 3b: reciprocal of the softmax denominator.
// ---------------------------------------------------------------------------
__global__ __launch_bounds__(256) void inv_k() {
    int i = blockIdx.x * blockDim.x + threadIdx.x;
    if (i < NN * 4) g_dinv[i] = 1.0f / g_den[i];
}

// ---------------------------------------------------------------------------
// Kernel 4: column-wise sum / sumsq of y = out*dinv + bias.
// ---------------------------------------------------------------------------
__global__ __launch_bounds__(128) void stats_k(const float* __restrict__ out,
                                               const float* __restrict__ bias) {
    const int c = threadIdx.x;
    const float b = bias[c];
    const int hsel = c >> 5;
    float s0 = 0.f, s1 = 0.f, q0 = 0.f, q1 = 0.f;

    int r = blockIdx.x;
    const int stride = gridDim.x;
    for (; r + 3 * stride < NN; r += 4 * stride) {
        float y0 = fmaf(out[(size_t)(r)              * FOUT + c], g_dinv[(r)              * 4 + hsel], b);
        float y1 = fmaf(out[(size_t)(r + stride)     * FOUT + c], g_dinv[(r + stride)     * 4 + hsel], b);
        float y2 = fmaf(out[(size_t)(r + 2 * stride) * FOUT + c], g_dinv[(r + 2 * stride) * 4 + hsel], b);
        float y3 = fmaf(out[(size_t)(r + 3 * stride) * FOUT + c], g_dinv[(r + 3 * stride) * 4 + hsel], b);
        s0 += y0 + y1; s1 += y2 + y3;
        q0 = fmaf(y0, y0, fmaf(y1, y1, q0));
        q1 = fmaf(y2, y2, fmaf(y3, y3, q1));
    }
    for (; r < NN; r += stride) {
        float y = fmaf(out[(size_t)r * FOUT + c], g_dinv[r * 4 + hsel], b);
        s0 += y; q0 = fmaf(y, y, q0);
    }
    atomicAdd(&g_stats[c], s0 + s1);
    atomicAdd(&g_stats[128 + c], q0 + q1);
}

// ---------------------------------------------------------------------------
// Kernel 5: finalize — normalize, BN affine, LeakyReLU(0.01), float4 in place.
// ---------------------------------------------------------------------------
__global__ __launch_bounds__(256) void final_k(float* __restrict__ out,
                                               const float* __restrict__ bias,
                                               const float* __restrict__ gamma,
                                               const float* __restrict__ beta) {
    size_t idx = (size_t)blockIdx.x * blockDim.x + threadIdx.x;     // over N*32
    if (idx >= (size_t)NN * 32) return;
    int cq = (int)(idx & 31);
    size_t r = idx >> 5;
    int c = cq * 4;
    float di = g_dinv[r * 4 + (c >> 5)];

    float4 v = *(float4*)(out + r * FOUT + c);
    const float invN = 1.0f / NN;
    float y[4] = {v.x, v.y, v.z, v.w};
#pragma unroll
    for (int j = 0; j < 4; j++) {
        int cc = c + j;
        float yy = fmaf(y[j], di, bias[cc]);
        float mu  = g_stats[cc] * invN;
        float var = fmaf(g_stats[128 + cc], invN, -mu * mu);
        float z = (yy - mu) * rsqrtf(var + BN_EPS) * gamma[cc] + beta[cc];
        y[j] = z < 0.f ? NEG_ACT * z : z;
    }
    *(float4*)(out + r * FOUT + c) = make_float4(y[0], y[1], y[2], y[3]);
}

// ---------------------------------------------------------------------------
extern "C" void kernel_launch(void* const* d_in, const int* in_sizes, int n_in,
                              void* d_out, int out_size) {
    const float* x       = (const float*)d_in[0];
    const int*   ei      = (const int*)  d_in[1];
    const float* W       = (const float*)d_in[2];
    const float* att_src = (const float*)d_in[3];
    const float* att_dst = (const float*)d_in[4];
    const float* bias    = (const float*)d_in[5];
    const float* gamma   = (const float*)d_in[6];
    const float* beta    = (const float*)d_in[7];
    float* out = (float*)d_out;

    gemm_tc<<<(NN + 127) / 128, 256>>>(x, W);
    node_init_k<<<(NN * 32 + 255) / 256, 256>>>(att_src, att_dst, out);
    edge_k<<<(EE * 32 + 255) / 256, 256>>>(ei, out);
    inv_k<<<(NN * 4 + 255) / 256, 256>>>();
    stats_k<<<2048, 128>>>(out, bias);
    final_k<<<(int)(((size_t)NN * 32 + 255) / 256), 256>>>(out, bias, gamma, beta);
}

// round 8
// speedup vs baseline: 1.9875x; 1.0604x over previous
#include <cuda_runtime.h>
#include <cuda_fp16.h>
#include <cstdint>

#define NN   50000
#define EE   800000
#define KIN  256
#define FOUT 128
#define NEG_ATT 0.2f
#define NEG_ACT 0.01f
#define BN_EPS  1e-5f

// Scratch (static device arrays — no allocations allowed)
__device__ __align__(16) __half2 g_hh[(size_t)NN * 64];    // fp16 h mirror for edge gather
__device__ __align__(16) float   g_s[NN * 4];              // a_src per node/head
__device__ __align__(16) float   g_d[NN * 4];              // a_dst per node/head
__device__ __align__(16) float   g_den[NN * 4];            // softmax denominator
__device__ __align__(16) float   g_dinv[NN * 4];           // 1 / denominator
__device__ __align__(16) float   g_stats[256];             // col sum[128], sumsq[128]

// ---------------------------------------------------------------------------
// Kernel 1: h = x @ W^T via 3xTF32 mma.m16n8k8 + FUSED attention scoring and
// self-loop init. Block 128x128 covers full output rows, so per-row head
// scores reduce inside one warp (shfl) + one 2KB smem broadcast of w.
// Writes: out = w_self * h (+), g_s/g_d/g_den, fp16 mirror g_hh. No fp32 g_h.
// ---------------------------------------------------------------------------
__device__ __forceinline__ uint32_t f2tf(float f) {
    uint32_t r; asm("cvt.rna.tf32.f32 %0, %1;" : "=r"(r) : "f"(f)); return r;
}

#define MMA_TF32(D, A0, A1, A2, A3, B0, B1)                                \
    asm volatile("mma.sync.aligned.m16n8k8.row.col.f32.tf32.tf32.f32 "     \
                 "{%0,%1,%2,%3},{%4,%5,%6,%7},{%8,%9},{%0,%1,%2,%3};"      \
                 : "+f"(D[0]), "+f"(D[1]), "+f"(D[2]), "+f"(D[3])          \
                 : "r"(A0), "r"(A1), "r"(A2), "r"(A3), "r"(B0), "r"(B1))

#define RS 48   // uints per smem row (192 bytes)

__global__ __launch_bounds__(256, 2) void gemm_tc(const float* __restrict__ x,
                                                  const float* __restrict__ W,
                                                  const float* __restrict__ att_src,
                                                  const float* __restrict__ att_dst,
                                                  float* __restrict__ out) {
    __shared__ __align__(16) uint32_t As[128 * RS];
    __shared__ __align__(16) uint32_t Bs[128 * RS];

    const int tid  = threadIdx.x;
    const int wid  = tid >> 5, lane = tid & 31;
    const int wm   = wid >> 1, wn = wid & 1;     // warp grid 4x2 (M x N)
    const int g    = lane >> 2, t = lane & 3;
    const int row0 = blockIdx.x * 128;

    const int sr   = tid >> 1;       // staging row 0..127
    const int sh   = tid & 1;        // k half: 0 or 8
    const int arow = row0 + sr;
    const bool aval = arow < NN;

    float va[8], vb[8];
    float acc[2][8][4];
#pragma unroll
    for (int mt = 0; mt < 2; mt++)
#pragma unroll
        for (int nt = 0; nt < 8; nt++)
#pragma unroll
            for (int i = 0; i < 4; i++) acc[mt][nt][i] = 0.f;

    {
        float4 a0 = make_float4(0.f,0.f,0.f,0.f), a1 = a0;
        if (aval) {
            a0 = *(const float4*)(x + (size_t)arow * KIN + sh * 8);
            a1 = *(const float4*)(x + (size_t)arow * KIN + sh * 8 + 4);
        }
        float4 b0 = *(const float4*)(W + (size_t)sr * KIN + sh * 8);
        float4 b1 = *(const float4*)(W + (size_t)sr * KIN + sh * 8 + 4);
        va[0]=a0.x; va[1]=a0.y; va[2]=a0.z; va[3]=a0.w;
        va[4]=a1.x; va[5]=a1.y; va[6]=a1.z; va[7]=a1.w;
        vb[0]=b0.x; vb[1]=b0.y; vb[2]=b0.z; vb[3]=b0.w;
        vb[4]=b1.x; vb[5]=b1.y; vb[6]=b1.z; vb[7]=b1.w;
    }

    uint32_t* Ap = As + sr * RS + sh * 16;
    uint32_t* Bp = Bs + sr * RS + sh * 16;

    for (int it = 0; it < 16; it++) {
        __syncthreads();
#pragma unroll
        for (int p = 0; p < 4; p++) {
            uint32_t h0 = f2tf(va[p]), h1 = f2tf(va[p + 4]);
            uint32_t l0 = f2tf(va[p] - __uint_as_float(h0));
            uint32_t l1 = f2tf(va[p + 4] - __uint_as_float(h1));
            *(uint4*)(Ap + p * 4) = make_uint4(h0, h1, l0, l1);
            h0 = f2tf(vb[p]); h1 = f2tf(vb[p + 4]);
            l0 = f2tf(vb[p] - __uint_as_float(h0));
            l1 = f2tf(vb[p + 4] - __uint_as_float(h1));
            *(uint4*)(Bp + p * 4) = make_uint4(h0, h1, l0, l1);
        }
        __syncthreads();

        if (it < 15) {
            int k0 = (it + 1) * 16;
            float4 a0 = make_float4(0.f,0.f,0.f,0.f), a1 = a0;
            if (aval) {
                a0 = *(const float4*)(x + (size_t)arow * KIN + k0 + sh * 8);
                a1 = *(const float4*)(x + (size_t)arow * KIN + k0 + sh * 8 + 4);
            }
            float4 b0 = *(const float4*)(W + (size_t)sr * KIN + k0 + sh * 8);
            float4 b1 = *(const float4*)(W + (size_t)sr * KIN + k0 + sh * 8 + 4);
            va[0]=a0.x; va[1]=a0.y; va[2]=a0.z; va[3]=a0.w;
            va[4]=a1.x; va[5]=a1.y; va[6]=a1.z; va[7]=a1.w;
            vb[0]=b0.x; vb[1]=b0.y; vb[2]=b0.z; vb[3]=b0.w;
            vb[4]=b1.x; vb[5]=b1.y; vb[6]=b1.z; vb[7]=b1.w;
        }

#pragma unroll
        for (int blk = 0; blk < 2; blk++) {
            uint32_t ah[2][4], al[2][4];
#pragma unroll
            for (int mt = 0; mt < 2; mt++) {
                int r = wm * 32 + mt * 16 + g;
                uint4 u = *(const uint4*)(As + r * RS + blk * 16 + t * 4);
                uint4 v = *(const uint4*)(As + (r + 8) * RS + blk * 16 + t * 4);
                ah[mt][0] = u.x; ah[mt][1] = v.x; ah[mt][2] = u.y; ah[mt][3] = v.y;
                al[mt][0] = u.z; al[mt][1] = v.z; al[mt][2] = u.w; al[mt][3] = v.w;
            }
#pragma unroll
            for (int nt = 0; nt < 8; nt++) {
                int c = wn * 64 + nt * 8 + g;
                uint4 v = *(const uint4*)(Bs + c * RS + blk * 16 + t * 4);
#pragma unroll
                for (int mt = 0; mt < 2; mt++) {
                    MMA_TF32(acc[mt][nt], ah[mt][0], ah[mt][1], ah[mt][2], ah[mt][3], v.x, v.y);
                    MMA_TF32(acc[mt][nt], ah[mt][0], ah[mt][1], ah[mt][2], ah[mt][3], v.z, v.w);
                    MMA_TF32(acc[mt][nt], al[mt][0], al[mt][1], al[mt][2], al[mt][3], v.x, v.y);
                }
            }
        }
    }

    __syncthreads();   // all MMA smem reads done; As reusable as w-broadcast

    // ---- fused attention scoring ----
    // partial idx = mt*4 + up*2 + hl  (up: row +8, hl: head within warp half)
    float ps[8], pd[8];
#pragma unroll
    for (int i = 0; i < 8; i++) { ps[i] = 0.f; pd[i] = 0.f; }
#pragma unroll
    for (int nt = 0; nt < 8; nt++) {
        int hl = nt >> 2;
        int head = 2 * wn + hl;
        int c0 = (nt & 3) * 8 + 2 * t;
        float as0 = att_src[head * 32 + c0], as1 = att_src[head * 32 + c0 + 1];
        float ad0 = att_dst[head * 32 + c0], ad1 = att_dst[head * 32 + c0 + 1];
#pragma unroll
        for (int mt = 0; mt < 2; mt++) {
            ps[mt*4 + hl]     = fmaf(acc[mt][nt][0], as0, fmaf(acc[mt][nt][1], as1, ps[mt*4 + hl]));
            pd[mt*4 + hl]     = fmaf(acc[mt][nt][0], ad0, fmaf(acc[mt][nt][1], ad1, pd[mt*4 + hl]));
            ps[mt*4 + 2 + hl] = fmaf(acc[mt][nt][2], as0, fmaf(acc[mt][nt][3], as1, ps[mt*4 + 2 + hl]));
            pd[mt*4 + 2 + hl] = fmaf(acc[mt][nt][2], ad0, fmaf(acc[mt][nt][3], ad1, pd[mt*4 + 2 + hl]));
        }
    }
#pragma unroll
    for (int i = 0; i < 8; i++) {
        ps[i] += __shfl_xor_sync(0xFFFFFFFFu, ps[i], 1);
        ps[i] += __shfl_xor_sync(0xFFFFFFFFu, ps[i], 2);
        pd[i] += __shfl_xor_sync(0xFFFFFFFFu, pd[i], 1);
        pd[i] += __shfl_xor_sync(0xFFFFFFFFu, pd[i], 2);
    }

    float* s_w = (float*)As;   // [128 rows][4 heads]
    if (t == 0) {
#pragma unroll
        for (int mt = 0; mt < 2; mt++)
#pragma unroll
        for (int up = 0; up < 2; up++)
#pragma unroll
        for (int hl = 0; hl < 2; hl++) {
            int lr = wm * 32 + mt * 16 + up * 8 + g;
            int head = 2 * wn + hl;
            float pss = ps[mt*4 + up*2 + hl], pdd = pd[mt*4 + up*2 + hl];
            float e = pss + pdd;
            e = e < 0.f ? NEG_ATT * e : e;
            float w = __expf(e);
            s_w[lr * 4 + head] = w;
            int gr = row0 + lr;
            if (gr < NN) {
                g_s[gr * 4 + head]   = pss;
                g_d[gr * 4 + head]   = pdd;
                g_den[gr * 4 + head] = w;
            }
        }
    }
    __syncthreads();

    // ---- write out = w_self * h  and fp16 mirror (h unscaled) ----
#pragma unroll
    for (int mt = 0; mt < 2; mt++) {
        int lr0 = wm * 32 + mt * 16 + g;
        int r = row0 + lr0;
#pragma unroll
        for (int nt = 0; nt < 8; nt++) {
            int col = wn * 64 + nt * 8 + 2 * t;
            int head = col >> 5;
            if (r < NN) {
                float w = s_w[lr0 * 4 + head];
                *(float2*)(out + (size_t)r * FOUT + col) =
                    make_float2(w * acc[mt][nt][0], w * acc[mt][nt][1]);
                g_hh[(size_t)r * 64 + (col >> 1)] =
                    __floats2half2_rn(acc[mt][nt][0], acc[mt][nt][1]);
            }
            if (r + 8 < NN) {
                float w = s_w[(lr0 + 8) * 4 + head];
                *(float2*)(out + (size_t)(r + 8) * FOUT + col) =
                    make_float2(w * acc[mt][nt][2], w * acc[mt][nt][3]);
                g_hh[(size_t)(r + 8) * 64 + (col >> 1)] =
                    __floats2half2_rn(acc[mt][nt][2], acc[mt][nt][3]);
            }
        }
    }
}

// ---------------------------------------------------------------------------
// Kernel 2: edge scatter. One warp per edge. fp16 gather of h, fp32 RED.128.
// ---------------------------------------------------------------------------
__global__ __launch_bounds__(256) void edge_k(const int* __restrict__ ei,
                                              float* __restrict__ out) {
    int warp = (int)((blockIdx.x * (unsigned)blockDim.x + threadIdx.x) >> 5);
    int lane = threadIdx.x & 31;
    if (warp >= EE) return;
    int src = ei[warp];
    int dst = ei[EE + warp];
    int head = lane >> 3;

    float e = g_s[src * 4 + head] + g_d[dst * 4 + head];
    e = e < 0.f ? NEG_ATT * e : e;
    float w = __expf(e);
    if ((lane & 7) == 0)
        atomicAdd(&g_den[dst * 4 + head], w);

    uint2 p = *(const uint2*)((const uint2*)g_hh + (size_t)src * 32 + lane);
    float2 lo = __half22float2(*(__half2*)&p.x);
    float2 hi = __half22float2(*(__half2*)&p.y);
    float* q = out + (size_t)dst * FOUT + lane * 4;
    asm volatile("red.global.add.v4.f32 [%0], {%1,%2,%3,%4};"
                 :: "l"(q), "f"(w * lo.x), "f"(w * lo.y),
                    "f"(w * hi.x), "f"(w * hi.y)
                 : "memory");
}

// ---------------------------------------------------------------------------
// Kernel 3: reciprocal of the softmax denominator. Block 0 zeroes BN stats.
// ---------------------------------------------------------------------------
__global__ __launch_bounds__(256) void inv_k() {
    if (blockIdx.x == 0) g_stats[threadIdx.x] = 0.f;
    int i = blockIdx.x * blockDim.x + threadIdx.x;
    if (i < NN * 4) g_dinv[i] = 1.0f / g_den[i];
}

// ---------------------------------------------------------------------------
// Kernel 4: column-wise sum / sumsq of y = out*dinv + bias.
// ---------------------------------------------------------------------------
__global__ __launch_bounds__(128) void stats_k(const float* __restrict__ out,
                                               const float* __restrict__ bias) {
    const int c = threadIdx.x;
    const float b = bias[c];
    const int hsel = c >> 5;
    float s0 = 0.f, s1 = 0.f, q0 = 0.f, q1 = 0.f;

    int r = blockIdx.x;
    const int stride = gridDim.x;
    for (; r + 3 * stride < NN; r += 4 * stride) {
        float y0 = fmaf(out[(size_t)(r)              * FOUT + c], g_dinv[(r)              * 4 + hsel], b);
        float y1 = fmaf(out[(size_t)(r + stride)     * FOUT + c], g_dinv[(r + stride)     * 4 + hsel], b);
        float y2 = fmaf(out[(size_t)(r + 2 * stride) * FOUT + c], g_dinv[(r + 2 * stride) * 4 + hsel], b);
        float y3 = fmaf(out[(size_t)(r + 3 * stride) * FOUT + c], g_dinv[(r + 3 * stride) * 4 + hsel], b);
        s0 += y0 + y1; s1 += y2 + y3;
        q0 = fmaf(y0, y0, fmaf(y1, y1, q0));
        q1 = fmaf(y2, y2, fmaf(y3, y3, q1));
    }
    for (; r < NN; r += stride) {
        float y = fmaf(out[(size_t)r * FOUT + c], g_dinv[r * 4 + hsel], b);
        s0 += y; q0 = fmaf(y, y, q0);
    }
    atomicAdd(&g_stats[c], s0 + s1);
    atomicAdd(&g_stats[128 + c], q0 + q1);
}

// ---------------------------------------------------------------------------
// Kernel 5: finalize — normalize, BN affine, LeakyReLU(0.01), float4 in place.
// ---------------------------------------------------------------------------
__global__ __launch_bounds__(256) void final_k(float* __restrict__ out,
                                               const float* __restrict__ bias,
                                               const float* __restrict__ gamma,
                                               const float* __restrict__ beta) {
    size_t idx = (size_t)blockIdx.x * blockDim.x + threadIdx.x;     // over N*32
    if (idx >= (size_t)NN * 32) return;
    int cq = (int)(idx & 31);
    size_t r = idx >> 5;
    int c = cq * 4;
    float di = g_dinv[r * 4 + (c >> 5)];

    float4 v = *(float4*)(out + r * FOUT + c);
    const float invN = 1.0f / NN;
    float y[4] = {v.x, v.y, v.z, v.w};
#pragma unroll
    for (int j = 0; j < 4; j++) {
        int cc = c + j;
        float yy = fmaf(y[j], di, bias[cc]);
        float mu  = g_stats[cc] * invN;
        float var = fmaf(g_stats[128 + cc], invN, -mu * mu);
        float z = (yy - mu) * rsqrtf(var + BN_EPS) * gamma[cc] + beta[cc];
        y[j] = z < 0.f ? NEG_ACT * z : z;
    }
    *(float4*)(out + r * FOUT + c) = make_float4(y[0], y[1], y[2], y[3]);
}

// ---------------------------------------------------------------------------
extern "C" void kernel_launch(void* const* d_in, const int* in_sizes, int n_in,
                              void* d_out, int out_size) {
    const float* x       = (const float*)d_in[0];
    const int*   ei      = (const int*)  d_in[1];
    const float* W       = (const float*)d_in[2];
    const float* att_src = (const float*)d_in[3];
    const float* att_dst = (const float*)d_in[4];
    const float* bias    = (const float*)d_in[5];
    const float* gamma   = (const float*)d_in[6];
    const float* beta    = (const float*)d_in[7];
    float* out = (float*)d_out;

    gemm_tc<<<(NN + 127) / 128, 256>>>(x, W, att_src, att_dst, out);
    edge_k<<<(EE * 32 + 255) / 256, 256>>>(ei, out);
    inv_k<<<(NN * 4 + 255) / 256, 256>>>();
    stats_k<<<2048, 128>>>(out, bias);
    final_k<<<(int)(((size_t)NN * 32 + 255) / 256), 256>>>(out, bias, gamma, beta);
}

// round 9
// speedup vs baseline: 2.5420x; 1.2790x over previous
#include <cuda_runtime.h>
#include <cuda_fp16.h>
#include <cstdint>

#define NN   50000
#define EE   800000
#define KIN  256
#define FOUT 128
#define NEG_ATT 0.2f
#define NEG_ACT 0.01f
#define BN_EPS  1e-5f
#define NB   196    // ceil(NN / 256)

// Scratch (static device arrays — no allocations allowed)
__device__ __align__(16) __half2 g_hh[(size_t)NN * 64];    // fp16 h mirror
__device__ __align__(16) float   g_s[NN * 4];              // a_src per node/head
__device__ __align__(16) float   g_d[NN * 4];              // a_dst per node/head
__device__ __align__(16) float   g_wself[NN * 4];          // exp(lrelu(s+d)) self-loop weight
__device__ __align__(16) float   g_stats[256];             // col sum[128], sumsq[128]
__device__ int g_deg[NN];                                  // in-degree histogram
__device__ int g_off[NN + 1];                              // CSR offsets
__device__ int g_cur[NN];                                  // scatter cursors
__device__ int g_srcs[EE];                                 // CSR: src per slot
__device__ int g_bsum[256];                                // per-block degree sums
__device__ int g_bpre[256];                                // exclusive block prefixes

// ---------------------------------------------------------------------------
// Kernel 1: h = x @ W^T via 3xTF32 mma + fused attention scoring.
// Writes g_hh (fp16 h), g_s, g_d, g_wself. Also zeroes g_deg / g_stats.
// ---------------------------------------------------------------------------
__device__ __forceinline__ uint32_t f2tf(float f) {
    uint32_t r; asm("cvt.rna.tf32.f32 %0, %1;" : "=r"(r) : "f"(f)); return r;
}

#define MMA_TF32(D, A0, A1, A2, A3, B0, B1)                                \
    asm volatile("mma.sync.aligned.m16n8k8.row.col.f32.tf32.tf32.f32 "     \
                 "{%0,%1,%2,%3},{%4,%5,%6,%7},{%8,%9},{%0,%1,%2,%3};"      \
                 : "+f"(D[0]), "+f"(D[1]), "+f"(D[2]), "+f"(D[3])          \
                 : "r"(A0), "r"(A1), "r"(A2), "r"(A3), "r"(B0), "r"(B1))

#define RS 48   // uints per smem row (192 bytes)

__global__ __launch_bounds__(256, 2) void gemm_tc(const float* __restrict__ x,
                                                  const float* __restrict__ W,
                                                  const float* __restrict__ att_src,
                                                  const float* __restrict__ att_dst) {
    __shared__ __align__(16) uint32_t As[128 * RS];
    __shared__ __align__(16) uint32_t Bs[128 * RS];

    const int tid  = threadIdx.x;
    const int wid  = tid >> 5, lane = tid & 31;
    const int wm   = wid >> 1, wn = wid & 1;     // warp grid 4x2 (M x N)
    const int g    = lane >> 2, t = lane & 3;
    const int row0 = blockIdx.x * 128;

    // zero scratch used later (g_deg for hist, g_stats for stats)
    int z = blockIdx.x * 256 + tid;
    if (z < NN) g_deg[z] = 0;
    if (blockIdx.x == 0) g_stats[tid] = 0.f;

    const int sr   = tid >> 1;       // staging row 0..127
    const int sh   = tid & 1;        // k half: 0 or 8
    const int arow = row0 + sr;
    const bool aval = arow < NN;

    float va[8], vb[8];
    float acc[2][8][4];
#pragma unroll
    for (int mt = 0; mt < 2; mt++)
#pragma unroll
        for (int nt = 0; nt < 8; nt++)
#pragma unroll
            for (int i = 0; i < 4; i++) acc[mt][nt][i] = 0.f;

    {
        float4 a0 = make_float4(0.f,0.f,0.f,0.f), a1 = a0;
        if (aval) {
            a0 = *(const float4*)(x + (size_t)arow * KIN + sh * 8);
            a1 = *(const float4*)(x + (size_t)arow * KIN + sh * 8 + 4);
        }
        float4 b0 = *(const float4*)(W + (size_t)sr * KIN + sh * 8);
        float4 b1 = *(const float4*)(W + (size_t)sr * KIN + sh * 8 + 4);
        va[0]=a0.x; va[1]=a0.y; va[2]=a0.z; va[3]=a0.w;
        va[4]=a1.x; va[5]=a1.y; va[6]=a1.z; va[7]=a1.w;
        vb[0]=b0.x; vb[1]=b0.y; vb[2]=b0.z; vb[3]=b0.w;
        vb[4]=b1.x; vb[5]=b1.y; vb[6]=b1.z; vb[7]=b1.w;
    }

    uint32_t* Ap = As + sr * RS + sh * 16;
    uint32_t* Bp = Bs + sr * RS + sh * 16;

    for (int it = 0; it < 16; it++) {
        __syncthreads();
#pragma unroll
        for (int p = 0; p < 4; p++) {
            uint32_t h0 = f2tf(va[p]), h1 = f2tf(va[p + 4]);
            uint32_t l0 = f2tf(va[p] - __uint_as_float(h0));
            uint32_t l1 = f2tf(va[p + 4] - __uint_as_float(h1));
            *(uint4*)(Ap + p * 4) = make_uint4(h0, h1, l0, l1);
            h0 = f2tf(vb[p]); h1 = f2tf(vb[p + 4]);
            l0 = f2tf(vb[p] - __uint_as_float(h0));
            l1 = f2tf(vb[p + 4] - __uint_as_float(h1));
            *(uint4*)(Bp + p * 4) = make_uint4(h0, h1, l0, l1);
        }
        __syncthreads();

        if (it < 15) {
            int k0 = (it + 1) * 16;
            float4 a0 = make_float4(0.f,0.f,0.f,0.f), a1 = a0;
            if (aval) {
                a0 = *(const float4*)(x + (size_t)arow * KIN + k0 + sh * 8);
                a1 = *(const float4*)(x + (size_t)arow * KIN + k0 + sh * 8 + 4);
            }
            float4 b0 = *(const float4*)(W + (size_t)sr * KIN + k0 + sh * 8);
            float4 b1 = *(const float4*)(W + (size_t)sr * KIN + k0 + sh * 8 + 4);
            va[0]=a0.x; va[1]=a0.y; va[2]=a0.z; va[3]=a0.w;
            va[4]=a1.x; va[5]=a1.y; va[6]=a1.z; va[7]=a1.w;
            vb[0]=b0.x; vb[1]=b0.y; vb[2]=b0.z; vb[3]=b0.w;
            vb[4]=b1.x; vb[5]=b1.y; vb[6]=b1.z; vb[7]=b1.w;
        }

#pragma unroll
        for (int blk = 0; blk < 2; blk++) {
            uint32_t ah[2][4], al[2][4];
#pragma unroll
            for (int mt = 0; mt < 2; mt++) {
                int r = wm * 32 + mt * 16 + g;
                uint4 u = *(const uint4*)(As + r * RS + blk * 16 + t * 4);
                uint4 v = *(const uint4*)(As + (r + 8) * RS + blk * 16 + t * 4);
                ah[mt][0] = u.x; ah[mt][1] = v.x; ah[mt][2] = u.y; ah[mt][3] = v.y;
                al[mt][0] = u.z; al[mt][1] = v.z; al[mt][2] = u.w; al[mt][3] = v.w;
            }
#pragma unroll
            for (int nt = 0; nt < 8; nt++) {
                int c = wn * 64 + nt * 8 + g;
                uint4 v = *(const uint4*)(Bs + c * RS + blk * 16 + t * 4);
#pragma unroll
                for (int mt = 0; mt < 2; mt++) {
                    MMA_TF32(acc[mt][nt], ah[mt][0], ah[mt][1], ah[mt][2], ah[mt][3], v.x, v.y);
                    MMA_TF32(acc[mt][nt], ah[mt][0], ah[mt][1], ah[mt][2], ah[mt][3], v.z, v.w);
                    MMA_TF32(acc[mt][nt], al[mt][0], al[mt][1], al[mt][2], al[mt][3], v.x, v.y);
                }
            }
        }
    }

    // ---- fused attention scoring ----
    float ps[8], pd[8];
#pragma unroll
    for (int i = 0; i < 8; i++) { ps[i] = 0.f; pd[i] = 0.f; }
#pragma unroll
    for (int nt = 0; nt < 8; nt++) {
        int hl = nt >> 2;
        int head = 2 * wn + hl;
        int c0 = (nt & 3) * 8 + 2 * t;
        float as0 = att_src[head * 32 + c0], as1 = att_src[head * 32 + c0 + 1];
        float ad0 = att_dst[head * 32 + c0], ad1 = att_dst[head * 32 + c0 + 1];
#pragma unroll
        for (int mt = 0; mt < 2; mt++) {
            ps[mt*4 + hl]     = fmaf(acc[mt][nt][0], as0, fmaf(acc[mt][nt][1], as1, ps[mt*4 + hl]));
            pd[mt*4 + hl]     = fmaf(acc[mt][nt][0], ad0, fmaf(acc[mt][nt][1], ad1, pd[mt*4 + hl]));
            ps[mt*4 + 2 + hl] = fmaf(acc[mt][nt][2], as0, fmaf(acc[mt][nt][3], as1, ps[mt*4 + 2 + hl]));
            pd[mt*4 + 2 + hl] = fmaf(acc[mt][nt][2], ad0, fmaf(acc[mt][nt][3], ad1, pd[mt*4 + 2 + hl]));
        }
    }
#pragma unroll
    for (int i = 0; i < 8; i++) {
        ps[i] += __shfl_xor_sync(0xFFFFFFFFu, ps[i], 1);
        ps[i] += __shfl_xor_sync(0xFFFFFFFFu, ps[i], 2);
        pd[i] += __shfl_xor_sync(0xFFFFFFFFu, pd[i], 1);
        pd[i] += __shfl_xor_sync(0xFFFFFFFFu, pd[i], 2);
    }
    if (t == 0) {
#pragma unroll
        for (int mt = 0; mt < 2; mt++)
#pragma unroll
        for (int up = 0; up < 2; up++)
#pragma unroll
        for (int hl = 0; hl < 2; hl++) {
            int gr = row0 + wm * 32 + mt * 16 + up * 8 + g;
            int head = 2 * wn + hl;
            float pss = ps[mt*4 + up*2 + hl], pdd = pd[mt*4 + up*2 + hl];
            if (gr < NN) {
                float e = pss + pdd;
                e = e < 0.f ? NEG_ATT * e : e;
                g_s[gr * 4 + head]     = pss;
                g_d[gr * 4 + head]     = pdd;
                g_wself[gr * 4 + head] = __expf(e);
            }
        }
    }

    // ---- fp16 mirror of h ----
#pragma unroll
    for (int mt = 0; mt < 2; mt++) {
        int r = row0 + wm * 32 + mt * 16 + g;
#pragma unroll
        for (int nt = 0; nt < 8; nt++) {
            int col = wn * 64 + nt * 8 + 2 * t;
            if (r < NN)
                g_hh[(size_t)r * 64 + (col >> 1)] =
                    __floats2half2_rn(acc[mt][nt][0], acc[mt][nt][1]);
            if (r + 8 < NN)
                g_hh[(size_t)(r + 8) * 64 + (col >> 1)] =
                    __floats2half2_rn(acc[mt][nt][2], acc[mt][nt][3]);
        }
    }
}

// ---------------------------------------------------------------------------
// Kernel 2: degree histogram over dst.
// ---------------------------------------------------------------------------
__global__ __launch_bounds__(256) void hist_k(const int* __restrict__ ei) {
    int e = blockIdx.x * blockDim.x + threadIdx.x;
    if (e < EE) atomicAdd(&g_deg[ei[EE + e]], 1);
}

// ---------------------------------------------------------------------------
// Kernels 3a/3b/3c: parallel 3-phase exclusive scan -> offsets + cursors.
// ---------------------------------------------------------------------------
__global__ __launch_bounds__(256) void blocksum_k() {
    __shared__ int red[256];
    int t = threadIdx.x;
    int i = blockIdx.x * 256 + t;
    red[t] = (i < NN) ? g_deg[i] : 0;
    __syncthreads();
#pragma unroll
    for (int o = 128; o; o >>= 1) {
        if (t < o) red[t] += red[t + o];
        __syncthreads();
    }
    if (t == 0) g_bsum[blockIdx.x] = red[0];
}

__global__ __launch_bounds__(256) void scanblk_k() {
    __shared__ int sc[256];
    int t = threadIdx.x;
    int v = (t < NB) ? g_bsum[t] : 0;
    sc[t] = v;
    __syncthreads();
#pragma unroll
    for (int o = 1; o < 256; o <<= 1) {
        int u = (t >= o) ? sc[t - o] : 0;
        __syncthreads();
        sc[t] += u;
        __syncthreads();
    }
    g_bpre[t] = sc[t] - v;
    if (t == 0) g_off[NN] = EE;
}

__global__ __launch_bounds__(256) void offsets_k() {
    __shared__ int sc[256];
    int t = threadIdx.x;
    int i = blockIdx.x * 256 + t;
    int v = (i < NN) ? g_deg[i] : 0;
    sc[t] = v;
    __syncthreads();
#pragma unroll
    for (int o = 1; o < 256; o <<= 1) {
        int u = (t >= o) ? sc[t - o] : 0;
        __syncthreads();
        sc[t] += u;
        __syncthreads();
    }
    int excl = sc[t] - v + g_bpre[blockIdx.x];
    if (i < NN) { g_off[i] = excl; g_cur[i] = excl; }
}

// ---------------------------------------------------------------------------
// Kernel 4: scatter edges into CSR slots.
// ---------------------------------------------------------------------------
__global__ __launch_bounds__(256) void scatter_k(const int* __restrict__ ei) {
    int e = blockIdx.x * blockDim.x + threadIdx.x;
    if (e >= EE) return;
    int dst = ei[EE + e];
    int pos = atomicAdd(&g_cur[dst], 1);
    g_srcs[pos] = ei[e];
}

// ---------------------------------------------------------------------------
// Kernel 5: gather-aggregate. One warp per dst node. Warp-cooperative index
// prefetch (ONE coalesced LDG covers up to 32 in-edges) + shfl broadcast ->
// every gather address is known immediately -> MLP ~ degree, no idx chain.
// Writes y = (w_self*h[n] + sum w*h[src]) / den + bias.
// ---------------------------------------------------------------------------
__global__ __launch_bounds__(256) void agg_k(const float* __restrict__ bias,
                                             float* __restrict__ out) {
    int n = (blockIdx.x * blockDim.x + threadIdx.x) >> 5;
    int lane = threadIdx.x & 31;
    if (n >= NN) return;
    const int head = lane >> 3;

    const float d_n = g_d[n * 4 + head];
    float den = g_wself[n * 4 + head];

    const uint2* __restrict__ hh = (const uint2*)g_hh;
    uint2 pself = hh[(size_t)n * 32 + lane];
    float2 sl = __half22float2(*(__half2*)&pself.x);
    float2 sh = __half22float2(*(__half2*)&pself.y);
    float a0 = den * sl.x, a1 = den * sl.y, a2 = den * sh.x, a3 = den * sh.y;

    const int beg = g_off[n];
    const int end = g_off[n + 1];
    for (int b = beg; b < end; b += 32) {
        int idx = b + lane;
        int my = (idx < end) ? g_srcs[idx] : 0;
        int cnt = min(32, end - b);
#pragma unroll 4
        for (int e = 0; e < cnt; e++) {
            int s = __shfl_sync(0xFFFFFFFFu, my, e);
            float sv = g_s[s * 4 + head];
            uint2 p = hh[(size_t)s * 32 + lane];
            float ee = sv + d_n;
            ee = ee < 0.f ? NEG_ATT * ee : ee;
            float w = __expf(ee);
            den += w;
            float2 lo = __half22float2(*(__half2*)&p.x);
            float2 hi = __half22float2(*(__half2*)&p.y);
            a0 = fmaf(w, lo.x, a0); a1 = fmaf(w, lo.y, a1);
            a2 = fmaf(w, hi.x, a2); a3 = fmaf(w, hi.y, a3);
        }
    }

    float rinv = 1.0f / den;
    float4 b4 = *(const float4*)(bias + lane * 4);
    *(float4*)(out + (size_t)n * FOUT + lane * 4) =
        make_float4(fmaf(a0, rinv, b4.x), fmaf(a1, rinv, b4.y),
                    fmaf(a2, rinv, b4.z), fmaf(a3, rinv, b4.w));
}

// ---------------------------------------------------------------------------
// Kernel 6: column-wise sum / sumsq of y (bias already included).
// ---------------------------------------------------------------------------
__global__ __launch_bounds__(128) void stats_k(const float* __restrict__ out) {
    const int c = threadIdx.x;
    float s0 = 0.f, s1 = 0.f, q0 = 0.f, q1 = 0.f;

    int r = blockIdx.x;
    const int stride = gridDim.x;
    for (; r + 3 * stride < NN; r += 4 * stride) {
        float y0 = out[(size_t)(r)              * FOUT + c];
        float y1 = out[(size_t)(r + stride)     * FOUT + c];
        float y2 = out[(size_t)(r + 2 * stride) * FOUT + c];
        float y3 = out[(size_t)(r + 3 * stride) * FOUT + c];
        s0 += y0 + y1; s1 += y2 + y3;
        q0 = fmaf(y0, y0, fmaf(y1, y1, q0));
        q1 = fmaf(y2, y2, fmaf(y3, y3, q1));
    }
    for (; r < NN; r += stride) {
        float y = out[(size_t)r * FOUT + c];
        s0 += y; q0 = fmaf(y, y, q0);
    }
    atomicAdd(&g_stats[c], s0 + s1);
    atomicAdd(&g_stats[128 + c], q0 + q1);
}

// ---------------------------------------------------------------------------
// Kernel 7: finalize — BN + LeakyReLU(0.01), float4 in place.
// ---------------------------------------------------------------------------
__global__ __launch_bounds__(256) void final_k(float* __restrict__ out,
                                               const float* __restrict__ gamma,
                                               const float* __restrict__ beta) {
    size_t idx = (size_t)blockIdx.x * blockDim.x + threadIdx.x;     // over N*32
    if (idx >= (size_t)NN * 32) return;
    int c = (int)(idx & 31) * 4;
    size_t r = idx >> 5;

    float4 v = *(float4*)(out + r * FOUT + c);
    const float invN = 1.0f / NN;
    float y[4] = {v.x, v.y, v.z, v.w};
#pragma unroll
    for (int j = 0; j < 4; j++) {
        int cc = c + j;
        float mu  = g_stats[cc] * invN;
        float var = fmaf(g_stats[128 + cc], invN, -mu * mu);
        float zz = (y[j] - mu) * rsqrtf(var + BN_EPS) * gamma[cc] + beta[cc];
        y[j] = zz < 0.f ? NEG_ACT * zz : zz;
    }
    *(float4*)(out + r * FOUT + c) = make_float4(y[0], y[1], y[2], y[3]);
}

// ---------------------------------------------------------------------------
extern "C" void kernel_launch(void* const* d_in, const int* in_sizes, int n_in,
                              void* d_out, int out_size) {
    const float* x       = (const float*)d_in[0];
    const int*   ei      = (const int*)  d_in[1];
    const float* W       = (const float*)d_in[2];
    const float* att_src = (const float*)d_in[3];
    const float* att_dst = (const float*)d_in[4];
    const float* bias    = (const float*)d_in[5];
    const float* gamma   = (const float*)d_in[6];
    const float* beta    = (const float*)d_in[7];
    float* out = (float*)d_out;

    gemm_tc<<<(NN + 127) / 128, 256>>>(x, W, att_src, att_dst);
    hist_k<<<(EE + 255) / 256, 256>>>(ei);
    blocksum_k<<<NB, 256>>>();
    scanblk_k<<<1, 256>>>();
    offsets_k<<<NB, 256>>>();
    scatter_k<<<(EE + 255) / 256, 256>>>(ei);
    agg_k<<<(NN * 32 + 255) / 256, 256>>>(bias, out);
    stats_k<<<2048, 128>>>(out);
    final_k<<<(int)(((size_t)NN * 32 + 255) / 256), 256>>>(out, gamma, beta);
}

// round 10
// speedup vs baseline: 2.5618x; 1.0078x over previous
#include <cuda_runtime.h>
#include <cuda_fp16.h>
#include <cstdint>

#define NN   50000
#define EE   800000
#define KIN  256
#define FOUT 128
#define NEG_ATT 0.2f
#define NEG_ACT 0.01f
#define BN_EPS  1e-5f
#define NB   196    // ceil(NN / 256)

// Scratch (static device arrays — no allocations allowed)
__device__ __align__(16) __half2 g_hh[(size_t)NN * 64];    // fp16 h mirror
__device__ __align__(16) float   g_s[NN * 4];              // a_src per node/head
__device__ __align__(16) float   g_d[NN * 4];              // a_dst per node/head
__device__ __align__(16) float   g_wself[NN * 4];          // exp(lrelu(s+d)) self weight
__device__ __align__(16) float   g_stats[256];             // col sum[128], sumsq[128]
__device__ int g_deg[NN];                                  // in-degree histogram
__device__ int g_off[NN + 1];                              // CSR offsets
__device__ int g_cur[NN];                                  // scatter cursors
__device__ int g_srcs[EE];                                 // CSR: src per slot
__device__ int g_bsum[256];                                // per-block degree sums
__device__ int g_bpre[256];                                // exclusive block prefixes

// ---------------------------------------------------------------------------
// Kernel 1: h = x @ W^T via 3xTF32 mma + fused attention scoring.
// Writes g_hh (fp16 h), g_s, g_d, g_wself. Also zeroes g_deg / g_stats.
// ---------------------------------------------------------------------------
__device__ __forceinline__ uint32_t f2tf(float f) {
    uint32_t r; asm("cvt.rna.tf32.f32 %0, %1;" : "=r"(r) : "f"(f)); return r;
}

#define MMA_TF32(D, A0, A1, A2, A3, B0, B1)                                \
    asm volatile("mma.sync.aligned.m16n8k8.row.col.f32.tf32.tf32.f32 "     \
                 "{%0,%1,%2,%3},{%4,%5,%6,%7},{%8,%9},{%0,%1,%2,%3};"      \
                 : "+f"(D[0]), "+f"(D[1]), "+f"(D[2]), "+f"(D[3])          \
                 : "r"(A0), "r"(A1), "r"(A2), "r"(A3), "r"(B0), "r"(B1))

#define RS 48   // uints per smem row (192 bytes)

__global__ __launch_bounds__(256, 2) void gemm_tc(const float* __restrict__ x,
                                                  const float* __restrict__ W,
                                                  const float* __restrict__ att_src,
                                                  const float* __restrict__ att_dst) {
    __shared__ __align__(16) uint32_t As[128 * RS];
    __shared__ __align__(16) uint32_t Bs[128 * RS];

    const int tid  = threadIdx.x;
    const int wid  = tid >> 5, lane = tid & 31;
    const int wm   = wid >> 1, wn = wid & 1;     // warp grid 4x2 (M x N)
    const int g    = lane >> 2, t = lane & 3;
    const int row0 = blockIdx.x * 128;

    int z = blockIdx.x * 256 + tid;
    if (z < NN) g_deg[z] = 0;
    if (blockIdx.x == 0) g_stats[tid] = 0.f;

    const int sr   = tid >> 1;       // staging row 0..127
    const int sh   = tid & 1;        // k half: 0 or 8
    const int arow = row0 + sr;
    const bool aval = arow < NN;

    float va[8], vb[8];
    float acc[2][8][4];
#pragma unroll
    for (int mt = 0; mt < 2; mt++)
#pragma unroll
        for (int nt = 0; nt < 8; nt++)
#pragma unroll
            for (int i = 0; i < 4; i++) acc[mt][nt][i] = 0.f;

    {
        float4 a0 = make_float4(0.f,0.f,0.f,0.f), a1 = a0;
        if (aval) {
            a0 = *(const float4*)(x + (size_t)arow * KIN + sh * 8);
            a1 = *(const float4*)(x + (size_t)arow * KIN + sh * 8 + 4);
        }
        float4 b0 = *(const float4*)(W + (size_t)sr * KIN + sh * 8);
        float4 b1 = *(const float4*)(W + (size_t)sr * KIN + sh * 8 + 4);
        va[0]=a0.x; va[1]=a0.y; va[2]=a0.z; va[3]=a0.w;
        va[4]=a1.x; va[5]=a1.y; va[6]=a1.z; va[7]=a1.w;
        vb[0]=b0.x; vb[1]=b0.y; vb[2]=b0.z; vb[3]=b0.w;
        vb[4]=b1.x; vb[5]=b1.y; vb[6]=b1.z; vb[7]=b1.w;
    }

    uint32_t* Ap = As + sr * RS + sh * 16;
    uint32_t* Bp = Bs + sr * RS + sh * 16;

    for (int it = 0; it < 16; it++) {
        __syncthreads();
#pragma unroll
        for (int p = 0; p < 4; p++) {
            uint32_t h0 = f2tf(va[p]), h1 = f2tf(va[p + 4]);
            uint32_t l0 = f2tf(va[p] - __uint_as_float(h0));
            uint32_t l1 = f2tf(va[p + 4] - __uint_as_float(h1));
            *(uint4*)(Ap + p * 4) = make_uint4(h0, h1, l0, l1);
            h0 = f2tf(vb[p]); h1 = f2tf(vb[p + 4]);
            l0 = f2tf(vb[p] - __uint_as_float(h0));
            l1 = f2tf(vb[p + 4] - __uint_as_float(h1));
            *(uint4*)(Bp + p * 4) = make_uint4(h0, h1, l0, l1);
        }
        __syncthreads();

        if (it < 15) {
            int k0 = (it + 1) * 16;
            float4 a0 = make_float4(0.f,0.f,0.f,0.f), a1 = a0;
            if (aval) {
                a0 = *(const float4*)(x + (size_t)arow * KIN + k0 + sh * 8);
                a1 = *(const float4*)(x + (size_t)arow * KIN + k0 + sh * 8 + 4);
            }
            float4 b0 = *(const float4*)(W + (size_t)sr * KIN + k0 + sh * 8);
            float4 b1 = *(const float4*)(W + (size_t)sr * KIN + k0 + sh * 8 + 4);
            va[0]=a0.x; va[1]=a0.y; va[2]=a0.z; va[3]=a0.w;
            va[4]=a1.x; va[5]=a1.y; va[6]=a1.z; va[7]=a1.w;
            vb[0]=b0.x; vb[1]=b0.y; vb[2]=b0.z; vb[3]=b0.w;
            vb[4]=b1.x; vb[5]=b1.y; vb[6]=b1.z; vb[7]=b1.w;
        }

#pragma unroll
        for (int blk = 0; blk < 2; blk++) {
            uint32_t ah[2][4], al[2][4];
#pragma unroll
            for (int mt = 0; mt < 2; mt++) {
                int r = wm * 32 + mt * 16 + g;
                uint4 u = *(const uint4*)(As + r * RS + blk * 16 + t * 4);
                uint4 v = *(const uint4*)(As + (r + 8) * RS + blk * 16 + t * 4);
                ah[mt][0] = u.x; ah[mt][1] = v.x; ah[mt][2] = u.y; ah[mt][3] = v.y;
                al[mt][0] = u.z; al[mt][1] = v.z; al[mt][2] = u.w; al[mt][3] = v.w;
            }
#pragma unroll
            for (int nt = 0; nt < 8; nt++) {
                int c = wn * 64 + nt * 8 + g;
                uint4 v = *(const uint4*)(Bs + c * RS + blk * 16 + t * 4);
#pragma unroll
                for (int mt = 0; mt < 2; mt++) {
                    MMA_TF32(acc[mt][nt], ah[mt][0], ah[mt][1], ah[mt][2], ah[mt][3], v.x, v.y);
                    MMA_TF32(acc[mt][nt], ah[mt][0], ah[mt][1], ah[mt][2], ah[mt][3], v.z, v.w);
                    MMA_TF32(acc[mt][nt], al[mt][0], al[mt][1], al[mt][2], al[mt][3], v.x, v.y);
                }
            }
        }
    }

    // ---- fused attention scoring ----
    float ps[8], pd[8];
#pragma unroll
    for (int i = 0; i < 8; i++) { ps[i] = 0.f; pd[i] = 0.f; }
#pragma unroll
    for (int nt = 0; nt < 8; nt++) {
        int hl = nt >> 2;
        int head = 2 * wn + hl;
        int c0 = (nt & 3) * 8 + 2 * t;
        float as0 = att_src[head * 32 + c0], as1 = att_src[head * 32 + c0 + 1];
        float ad0 = att_dst[head * 32 + c0], ad1 = att_dst[head * 32 + c0 + 1];
#pragma unroll
        for (int mt = 0; mt < 2; mt++) {
            ps[mt*4 + hl]     = fmaf(acc[mt][nt][0], as0, fmaf(acc[mt][nt][1], as1, ps[mt*4 + hl]));
            pd[mt*4 + hl]     = fmaf(acc[mt][nt][0], ad0, fmaf(acc[mt][nt][1], ad1, pd[mt*4 + hl]));
            ps[mt*4 + 2 + hl] = fmaf(acc[mt][nt][2], as0, fmaf(acc[mt][nt][3], as1, ps[mt*4 + 2 + hl]));
            pd[mt*4 + 2 + hl] = fmaf(acc[mt][nt][2], ad0, fmaf(acc[mt][nt][3], ad1, pd[mt*4 + 2 + hl]));
        }
    }
#pragma unroll
    for (int i = 0; i < 8; i++) {
        ps[i] += __shfl_xor_sync(0xFFFFFFFFu, ps[i], 1);
        ps[i] += __shfl_xor_sync(0xFFFFFFFFu, ps[i], 2);
        pd[i] += __shfl_xor_sync(0xFFFFFFFFu, pd[i], 1);
        pd[i] += __shfl_xor_sync(0xFFFFFFFFu, pd[i], 2);
    }
    if (t == 0) {
#pragma unroll
        for (int mt = 0; mt < 2; mt++)
#pragma unroll
        for (int up = 0; up < 2; up++)
#pragma unroll
        for (int hl = 0; hl < 2; hl++) {
            int gr = row0 + wm * 32 + mt * 16 + up * 8 + g;
            int head = 2 * wn + hl;
            float pss = ps[mt*4 + up*2 + hl], pdd = pd[mt*4 + up*2 + hl];
            if (gr < NN) {
                float e = pss + pdd;
                e = e < 0.f ? NEG_ATT * e : e;
                g_s[gr * 4 + head]     = pss;
                g_d[gr * 4 + head]     = pdd;
                g_wself[gr * 4 + head] = __expf(e);
            }
        }
    }

    // ---- fp16 mirror of h ----
#pragma unroll
    for (int mt = 0; mt < 2; mt++) {
        int r = row0 + wm * 32 + mt * 16 + g;
#pragma unroll
        for (int nt = 0; nt < 8; nt++) {
            int col = wn * 64 + nt * 8 + 2 * t;
            if (r < NN)
                g_hh[(size_t)r * 64 + (col >> 1)] =
                    __floats2half2_rn(acc[mt][nt][0], acc[mt][nt][1]);
            if (r + 8 < NN)
                g_hh[(size_t)(r + 8) * 64 + (col >> 1)] =
                    __floats2half2_rn(acc[mt][nt][2], acc[mt][nt][3]);
        }
    }
}

// ---------------------------------------------------------------------------
// Kernel 2: degree histogram over dst.
// ---------------------------------------------------------------------------
__global__ __launch_bounds__(256) void hist_k(const int* __restrict__ ei) {
    int e = blockIdx.x * blockDim.x + threadIdx.x;
    if (e < EE) atomicAdd(&g_deg[ei[EE + e]], 1);
}

// ---------------------------------------------------------------------------
// Kernels 3a/3b/3c: parallel 3-phase exclusive scan -> offsets + cursors.
// ---------------------------------------------------------------------------
__global__ __launch_bounds__(256) void blocksum_k() {
    __shared__ int red[256];
    int t = threadIdx.x;
    int i = blockIdx.x * 256 + t;
    red[t] = (i < NN) ? g_deg[i] : 0;
    __syncthreads();
#pragma unroll
    for (int o = 128; o; o >>= 1) {
        if (t < o) red[t] += red[t + o];
        __syncthreads();
    }
    if (t == 0) g_bsum[blockIdx.x] = red[0];
}

__global__ __launch_bounds__(256) void scanblk_k() {
    __shared__ int sc[256];
    int t = threadIdx.x;
    int v = (t < NB) ? g_bsum[t] : 0;
    sc[t] = v;
    __syncthreads();
#pragma unroll
    for (int o = 1; o < 256; o <<= 1) {
        int u = (t >= o) ? sc[t - o] : 0;
        __syncthreads();
        sc[t] += u;
        __syncthreads();
    }
    g_bpre[t] = sc[t] - v;
    if (t == 0) g_off[NN] = EE;
}

__global__ __launch_bounds__(256) void offsets_k() {
    __shared__ int sc[256];
    int t = threadIdx.x;
    int i = blockIdx.x * 256 + t;
    int v = (i < NN) ? g_deg[i] : 0;
    sc[t] = v;
    __syncthreads();
#pragma unroll
    for (int o = 1; o < 256; o <<= 1) {
        int u = (t >= o) ? sc[t - o] : 0;
        __syncthreads();
        sc[t] += u;
        __syncthreads();
    }
    int excl = sc[t] - v + g_bpre[blockIdx.x];
    if (i < NN) { g_off[i] = excl; g_cur[i] = excl; }
}

// ---------------------------------------------------------------------------
// Kernel 4: scatter edges into CSR slots.
// ---------------------------------------------------------------------------
__global__ __launch_bounds__(256) void scatter_k(const int* __restrict__ ei) {
    int e = blockIdx.x * blockDim.x + threadIdx.x;
    if (e >= EE) return;
    int dst = ei[EE + e];
    int pos = atomicAdd(&g_cur[dst], 1);
    g_srcs[pos] = ei[e];
}

// ---------------------------------------------------------------------------
// Kernel 5: gather-aggregate + FUSED BN stats. One warp per dst node
// (grid 6250 x 8 warps = exactly NN, no early exit). After computing y, each
// block reduces column sum/sumsq into smem (lane c-mapping is warp-invariant)
// and flushes 256 global atomics. Replaces the whole stats_k pass.
// ---------------------------------------------------------------------------
__global__ __launch_bounds__(256) void agg_k(const float* __restrict__ bias,
                                             float* __restrict__ out) {
    __shared__ float s_acc[256];   // [0:128) col sums, [128:256) col sumsqs
    if (threadIdx.x < 256) s_acc[threadIdx.x] = 0.f;
    __syncthreads();

    int n = (blockIdx.x * blockDim.x + threadIdx.x) >> 5;
    int lane = threadIdx.x & 31;
    const int head = lane >> 3;

    const float d_n = g_d[n * 4 + head];
    float den = g_wself[n * 4 + head];

    const uint2* __restrict__ hh = (const uint2*)g_hh;
    uint2 pself = hh[(size_t)n * 32 + lane];
    float2 sl = __half22float2(*(__half2*)&pself.x);
    float2 shh = __half22float2(*(__half2*)&pself.y);
    float a0 = den * sl.x, a1 = den * sl.y, a2 = den * shh.x, a3 = den * shh.y;

    const int beg = g_off[n];
    const int end = g_off[n + 1];
    for (int b = beg; b < end; b += 32) {
        int idx = b + lane;
        int my = (idx < end) ? g_srcs[idx] : 0;
        int cnt = min(32, end - b);
#pragma unroll 4
        for (int e = 0; e < cnt; e++) {
            int s = __shfl_sync(0xFFFFFFFFu, my, e);
            float sv = g_s[s * 4 + head];
            uint2 p = hh[(size_t)s * 32 + lane];
            float ee = sv + d_n;
            ee = ee < 0.f ? NEG_ATT * ee : ee;
            float w = __expf(ee);
            den += w;
            float2 lo = __half22float2(*(__half2*)&p.x);
            float2 hi = __half22float2(*(__half2*)&p.y);
            a0 = fmaf(w, lo.x, a0); a1 = fmaf(w, lo.y, a1);
            a2 = fmaf(w, hi.x, a2); a3 = fmaf(w, hi.y, a3);
        }
    }

    float rinv = 1.0f / den;
    float4 b4 = *(const float4*)(bias + lane * 4);
    float y0 = fmaf(a0, rinv, b4.x), y1 = fmaf(a1, rinv, b4.y);
    float y2 = fmaf(a2, rinv, b4.z), y3 = fmaf(a3, rinv, b4.w);
    *(float4*)(out + (size_t)n * FOUT + lane * 4) = make_float4(y0, y1, y2, y3);

    // block-level BN stats reduction (cols = lane*4+j, warp-invariant)
    int c = lane * 4;
    atomicAdd(&s_acc[c + 0], y0); atomicAdd(&s_acc[128 + c + 0], y0 * y0);
    atomicAdd(&s_acc[c + 1], y1); atomicAdd(&s_acc[128 + c + 1], y1 * y1);
    atomicAdd(&s_acc[c + 2], y2); atomicAdd(&s_acc[128 + c + 2], y2 * y2);
    atomicAdd(&s_acc[c + 3], y3); atomicAdd(&s_acc[128 + c + 3], y3 * y3);
    __syncthreads();
    atomicAdd(&g_stats[threadIdx.x], s_acc[threadIdx.x]);
}

// ---------------------------------------------------------------------------
// Kernel 6: finalize — BN + LeakyReLU(0.01), float4 in place.
// ---------------------------------------------------------------------------
__global__ __launch_bounds__(256) void final_k(float* __restrict__ out,
                                               const float* __restrict__ gamma,
                                               const float* __restrict__ beta) {
    size_t idx = (size_t)blockIdx.x * blockDim.x + threadIdx.x;     // over N*32
    if (idx >= (size_t)NN * 32) return;
    int c = (int)(idx & 31) * 4;
    size_t r = idx >> 5;

    float4 v = *(float4*)(out + r * FOUT + c);
    const float invN = 1.0f / NN;
    float y[4] = {v.x, v.y, v.z, v.w};
#pragma unroll
    for (int j = 0; j < 4; j++) {
        int cc = c + j;
        float mu  = g_stats[cc] * invN;
        float var = fmaf(g_stats[128 + cc], invN, -mu * mu);
        float zz = (y[j] - mu) * rsqrtf(var + BN_EPS) * gamma[cc] + beta[cc];
        y[j] = zz < 0.f ? NEG_ACT * zz : zz;
    }
    *(float4*)(out + r * FOUT + c) = make_float4(y[0], y[1], y[2], y[3]);
}

// ---------------------------------------------------------------------------
extern "C" void kernel_launch(void* const* d_in, const int* in_sizes, int n_in,
                              void* d_out, int out_size) {
    const float* x       = (const float*)d_in[0];
    const int*   ei      = (const int*)  d_in[1];
    const float* W       = (const float*)d_in[2];
    const float* att_src = (const float*)d_in[3];
    const float* att_dst = (const float*)d_in[4];
    const float* bias    = (const float*)d_in[5];
    const float* gamma   = (const float*)d_in[6];
    const float* beta    = (const float*)d_in[7];
    float* out = (float*)d_out;

    gemm_tc<<<(NN + 127) / 128, 256>>>(x, W, att_src, att_dst);
    hist_k<<<(EE + 255) / 256, 256>>>(ei);
    blocksum_k<<<NB, 256>>>();
    scanblk_k<<<1, 256>>>();
    offsets_k<<<NB, 256>>>();
    scatter_k<<<(EE + 255) / 256, 256>>>(ei);
    agg_k<<<NN / 8, 256>>>(bias, out);
    final_k<<<(int)(((size_t)NN * 32 + 255) / 256), 256>>>(out, gamma, beta);
}

// round 11
// speedup vs baseline: 2.8409x; 1.1089x over previous
#include <cuda_runtime.h>
#include <cuda_fp16.h>
#include <cstdint>

#define NN   50000
#define EE   800000
#define KIN  256
#define FOUT 128
#define NEG_ATT 0.2f
#define NEG_ACT 0.01f
#define BN_EPS  1e-5f
#define NB   196    // ceil(NN / 256)

// Scratch (static device arrays — no allocations allowed).
// g_deg is zero at module load (BSS) and re-zeroed at the end of final_k,
// so every kernel_launch invocation starts with g_deg == 0.
__device__ __align__(16) __half2 g_hh[(size_t)NN * 64];    // fp16 h mirror
__device__ __align__(16) float   g_s[NN * 4];              // a_src per node/head
__device__ __align__(16) float   g_d[NN * 4];              // a_dst per node/head
__device__ __align__(16) float   g_wself[NN * 4];          // exp(lrelu(s+d)) self weight
__device__ __align__(16) float   g_stats[256];             // col sum[128], sumsq[128]
__device__ int g_deg[NN];                                  // in-degree histogram
__device__ int g_off[NN + 1];                              // CSR offsets
__device__ int g_cur[NN];                                  // scatter cursors
__device__ int g_srcs[EE];                                 // CSR: src per slot
__device__ int g_bsum[256];                                // per-block degree sums
__device__ int g_bpre[256];                                // exclusive block prefixes

// ---------------------------------------------------------------------------
// Kernel 1: h = x @ W^T via 3xTF32 mma + fused attention scoring.
// Writes g_hh (fp16 h), g_s, g_d, g_wself. Zeroes g_stats (block 0).
// NOTE: must NOT touch g_deg — the CSR branch runs concurrently.
// ---------------------------------------------------------------------------
__device__ __forceinline__ uint32_t f2tf(float f) {
    uint32_t r; asm("cvt.rna.tf32.f32 %0, %1;" : "=r"(r) : "f"(f)); return r;
}

#define MMA_TF32(D, A0, A1, A2, A3, B0, B1)                                \
    asm volatile("mma.sync.aligned.m16n8k8.row.col.f32.tf32.tf32.f32 "     \
                 "{%0,%1,%2,%3},{%4,%5,%6,%7},{%8,%9},{%0,%1,%2,%3};"      \
                 : "+f"(D[0]), "+f"(D[1]), "+f"(D[2]), "+f"(D[3])          \
                 : "r"(A0), "r"(A1), "r"(A2), "r"(A3), "r"(B0), "r"(B1))

#define RS 48   // uints per smem row (192 bytes)

__global__ __launch_bounds__(256, 2) void gemm_tc(const float* __restrict__ x,
                                                  const float* __restrict__ W,
                                                  const float* __restrict__ att_src,
                                                  const float* __restrict__ att_dst) {
    __shared__ __align__(16) uint32_t As[128 * RS];
    __shared__ __align__(16) uint32_t Bs[128 * RS];

    const int tid  = threadIdx.x;
    const int wid  = tid >> 5, lane = tid & 31;
    const int wm   = wid >> 1, wn = wid & 1;     // warp grid 4x2 (M x N)
    const int g    = lane >> 2, t = lane & 3;
    const int row0 = blockIdx.x * 128;

    if (blockIdx.x == 0) g_stats[tid] = 0.f;

    const int sr   = tid >> 1;       // staging row 0..127
    const int sh   = tid & 1;        // k half: 0 or 8
    const int arow = row0 + sr;
    const bool aval = arow < NN;

    float va[8], vb[8];
    float acc[2][8][4];
#pragma unroll
    for (int mt = 0; mt < 2; mt++)
#pragma unroll
        for (int nt = 0; nt < 8; nt++)
#pragma unroll
            for (int i = 0; i < 4; i++) acc[mt][nt][i] = 0.f;

    {
        float4 a0 = make_float4(0.f,0.f,0.f,0.f), a1 = a0;
        if (aval) {
            a0 = *(const float4*)(x + (size_t)arow * KIN + sh * 8);
            a1 = *(const float4*)(x + (size_t)arow * KIN + sh * 8 + 4);
        }
        float4 b0 = *(const float4*)(W + (size_t)sr * KIN + sh * 8);
        float4 b1 = *(const float4*)(W + (size_t)sr * KIN + sh * 8 + 4);
        va[0]=a0.x; va[1]=a0.y; va[2]=a0.z; va[3]=a0.w;
        va[4]=a1.x; va[5]=a1.y; va[6]=a1.z; va[7]=a1.w;
        vb[0]=b0.x; vb[1]=b0.y; vb[2]=b0.z; vb[3]=b0.w;
        vb[4]=b1.x; vb[5]=b1.y; vb[6]=b1.z; vb[7]=b1.w;
    }

    uint32_t* Ap = As + sr * RS + sh * 16;
    uint32_t* Bp = Bs + sr * RS + sh * 16;

    for (int it = 0; it < 16; it++) {
        __syncthreads();
#pragma unroll
        for (int p = 0; p < 4; p++) {
            uint32_t h0 = f2tf(va[p]), h1 = f2tf(va[p + 4]);
            uint32_t l0 = f2tf(va[p] - __uint_as_float(h0));
            uint32_t l1 = f2tf(va[p + 4] - __uint_as_float(h1));
            *(uint4*)(Ap + p * 4) = make_uint4(h0, h1, l0, l1);
            h0 = f2tf(vb[p]); h1 = f2tf(vb[p + 4]);
            l0 = f2tf(vb[p] - __uint_as_float(h0));
            l1 = f2tf(vb[p + 4] - __uint_as_float(h1));
            *(uint4*)(Bp + p * 4) = make_uint4(h0, h1, l0, l1);
        }
        __syncthreads();

        if (it < 15) {
            int k0 = (it + 1) * 16;
            float4 a0 = make_float4(0.f,0.f,0.f,0.f), a1 = a0;
            if (aval) {
                a0 = *(const float4*)(x + (size_t)arow * KIN + k0 + sh * 8);
                a1 = *(const float4*)(x + (size_t)arow * KIN + k0 + sh * 8 + 4);
            }
            float4 b0 = *(const float4*)(W + (size_t)sr * KIN + k0 + sh * 8);
            float4 b1 = *(const float4*)(W + (size_t)sr * KIN + k0 + sh * 8 + 4);
            va[0]=a0.x; va[1]=a0.y; va[2]=a0.z; va[3]=a0.w;
            va[4]=a1.x; va[5]=a1.y; va[6]=a1.z; va[7]=a1.w;
            vb[0]=b0.x; vb[1]=b0.y; vb[2]=b0.z; vb[3]=b0.w;
            vb[4]=b1.x; vb[5]=b1.y; vb[6]=b1.z; vb[7]=b1.w;
        }

#pragma unroll
        for (int blk = 0; blk < 2; blk++) {
            uint32_t ah[2][4], al[2][4];
#pragma unroll
            for (int mt = 0; mt < 2; mt++) {
                int r = wm * 32 + mt * 16 + g;
                uint4 u = *(const uint4*)(As + r * RS + blk * 16 + t * 4);
                uint4 v = *(const uint4*)(As + (r + 8) * RS + blk * 16 + t * 4);
                ah[mt][0] = u.x; ah[mt][1] = v.x; ah[mt][2] = u.y; ah[mt][3] = v.y;
                al[mt][0] = u.z; al[mt][1] = v.z; al[mt][2] = u.w; al[mt][3] = v.w;
            }
#pragma unroll
            for (int nt = 0; nt < 8; nt++) {
                int c = wn * 64 + nt * 8 + g;
                uint4 v = *(const uint4*)(Bs + c * RS + blk * 16 + t * 4);
#pragma unroll
                for (int mt = 0; mt < 2; mt++) {
                    MMA_TF32(acc[mt][nt], ah[mt][0], ah[mt][1], ah[mt][2], ah[mt][3], v.x, v.y);
                    MMA_TF32(acc[mt][nt], ah[mt][0], ah[mt][1], ah[mt][2], ah[mt][3], v.z, v.w);
                    MMA_TF32(acc[mt][nt], al[mt][0], al[mt][1], al[mt][2], al[mt][3], v.x, v.y);
                }
            }
        }
    }

    // ---- fused attention scoring ----
    float ps[8], pd[8];
#pragma unroll
    for (int i = 0; i < 8; i++) { ps[i] = 0.f; pd[i] = 0.f; }
#pragma unroll
    for (int nt = 0; nt < 8; nt++) {
        int hl = nt >> 2;
        int head = 2 * wn + hl;
        int c0 = (nt & 3) * 8 + 2 * t;
        float as0 = att_src[head * 32 + c0], as1 = att_src[head * 32 + c0 + 1];
        float ad0 = att_dst[head * 32 + c0], ad1 = att_dst[head * 32 + c0 + 1];
#pragma unroll
        for (int mt = 0; mt < 2; mt++) {
            ps[mt*4 + hl]     = fmaf(acc[mt][nt][0], as0, fmaf(acc[mt][nt][1], as1, ps[mt*4 + hl]));
            pd[mt*4 + hl]     = fmaf(acc[mt][nt][0], ad0, fmaf(acc[mt][nt][1], ad1, pd[mt*4 + hl]));
            ps[mt*4 + 2 + hl] = fmaf(acc[mt][nt][2], as0, fmaf(acc[mt][nt][3], as1, ps[mt*4 + 2 + hl]));
            pd[mt*4 + 2 + hl] = fmaf(acc[mt][nt][2], ad0, fmaf(acc[mt][nt][3], ad1, pd[mt*4 + 2 + hl]));
        }
    }
#pragma unroll
    for (int i = 0; i < 8; i++) {
        ps[i] += __shfl_xor_sync(0xFFFFFFFFu, ps[i], 1);
        ps[i] += __shfl_xor_sync(0xFFFFFFFFu, ps[i], 2);
        pd[i] += __shfl_xor_sync(0xFFFFFFFFu, pd[i], 1);
        pd[i] += __shfl_xor_sync(0xFFFFFFFFu, pd[i], 2);
    }
    if (t == 0) {
#pragma unroll
        for (int mt = 0; mt < 2; mt++)
#pragma unroll
        for (int up = 0; up < 2; up++)
#pragma unroll
        for (int hl = 0; hl < 2; hl++) {
            int gr = row0 + wm * 32 + mt * 16 + up * 8 + g;
            int head = 2 * wn + hl;
            float pss = ps[mt*4 + up*2 + hl], pdd = pd[mt*4 + up*2 + hl];
            if (gr < NN) {
                float e = pss + pdd;
                e = e < 0.f ? NEG_ATT * e : e;
                g_s[gr * 4 + head]     = pss;
                g_d[gr * 4 + head]     = pdd;
                g_wself[gr * 4 + head] = __expf(e);
            }
        }
    }

    // ---- fp16 mirror of h ----
#pragma unroll
    for (int mt = 0; mt < 2; mt++) {
        int r = row0 + wm * 32 + mt * 16 + g;
#pragma unroll
        for (int nt = 0; nt < 8; nt++) {
            int col = wn * 64 + nt * 8 + 2 * t;
            if (r < NN)
                g_hh[(size_t)r * 64 + (col >> 1)] =
                    __floats2half2_rn(acc[mt][nt][0], acc[mt][nt][1]);
            if (r + 8 < NN)
                g_hh[(size_t)(r + 8) * 64 + (col >> 1)] =
                    __floats2half2_rn(acc[mt][nt][2], acc[mt][nt][3]);
        }
    }
}

// ---------------------------------------------------------------------------
// Kernel 2: degree histogram over dst (g_deg pre-zeroed by previous call).
// ---------------------------------------------------------------------------
__global__ __launch_bounds__(256) void hist_k(const int* __restrict__ ei) {
    int e = blockIdx.x * blockDim.x + threadIdx.x;
    if (e < EE) atomicAdd(&g_deg[ei[EE + e]], 1);
}

// ---------------------------------------------------------------------------
// Kernels 3a/3b/3c: parallel 3-phase exclusive scan -> offsets + cursors.
// ---------------------------------------------------------------------------
__global__ __launch_bounds__(256) void blocksum_k() {
    __shared__ int red[256];
    int t = threadIdx.x;
    int i = blockIdx.x * 256 + t;
    red[t] = (i < NN) ? g_deg[i] : 0;
    __syncthreads();
#pragma unroll
    for (int o = 128; o; o >>= 1) {
        if (t < o) red[t] += red[t + o];
        __syncthreads();
    }
    if (t == 0) g_bsum[blockIdx.x] = red[0];
}

__global__ __launch_bounds__(256) void scanblk_k() {
    __shared__ int sc[256];
    int t = threadIdx.x;
    int v = (t < NB) ? g_bsum[t] : 0;
    sc[t] = v;
    __syncthreads();
#pragma unroll
    for (int o = 1; o < 256; o <<= 1) {
        int u = (t >= o) ? sc[t - o] : 0;
        __syncthreads();
        sc[t] += u;
        __syncthreads();
    }
    g_bpre[t] = sc[t] - v;
    if (t == 0) g_off[NN] = EE;
}

__global__ __launch_bounds__(256) void offsets_k() {
    __shared__ int sc[256];
    int t = threadIdx.x;
    int i = blockIdx.x * 256 + t;
    int v = (i < NN) ? g_deg[i] : 0;
    sc[t] = v;
    __syncthreads();
#pragma unroll
    for (int o = 1; o < 256; o <<= 1) {
        int u = (t >= o) ? sc[t - o] : 0;
        __syncthreads();
        sc[t] += u;
        __syncthreads();
    }
    int excl = sc[t] - v + g_bpre[blockIdx.x];
    if (i < NN) { g_off[i] = excl; g_cur[i] = excl; }
}

// ---------------------------------------------------------------------------
// Kernel 4: scatter edges into CSR slots.
// ---------------------------------------------------------------------------
__global__ __launch_bounds__(256) void scatter_k(const int* __restrict__ ei) {
    int e = blockIdx.x * blockDim.x + threadIdx.x;
    if (e >= EE) return;
    int dst = ei[EE + e];
    int pos = atomicAdd(&g_cur[dst], 1);
    g_srcs[pos] = ei[e];
}

// ---------------------------------------------------------------------------
// Kernel 5: gather-aggregate + fused BN stats. One warp per dst node.
// ---------------------------------------------------------------------------
__global__ __launch_bounds__(256) void agg_k(const float* __restrict__ bias,
                                             float* __restrict__ out) {
    __shared__ float s_acc[256];
    if (threadIdx.x < 256) s_acc[threadIdx.x] = 0.f;
    __syncthreads();

    int n = (blockIdx.x * blockDim.x + threadIdx.x) >> 5;
    int lane = threadIdx.x & 31;
    const int head = lane >> 3;

    const float d_n = g_d[n * 4 + head];
    float den = g_wself[n * 4 + head];

    const uint2* __restrict__ hh = (const uint2*)g_hh;
    uint2 pself = hh[(size_t)n * 32 + lane];
    float2 sl = __half22float2(*(__half2*)&pself.x);
    float2 shh = __half22float2(*(__half2*)&pself.y);
    float a0 = den * sl.x, a1 = den * sl.y, a2 = den * shh.x, a3 = den * shh.y;

    const int beg = g_off[n];
    const int end = g_off[n + 1];
    for (int b = beg; b < end; b += 32) {
        int idx = b + lane;
        int my = (idx < end) ? g_srcs[idx] : 0;
        int cnt = min(32, end - b);
#pragma unroll 4
        for (int e = 0; e < cnt; e++) {
            int s = __shfl_sync(0xFFFFFFFFu, my, e);
            float sv = g_s[s * 4 + head];
            uint2 p = hh[(size_t)s * 32 + lane];
            float ee = sv + d_n;
            ee = ee < 0.f ? NEG_ATT * ee : ee;
            float w = __expf(ee);
            den += w;
            float2 lo = __half22float2(*(__half2*)&p.x);
            float2 hi = __half22float2(*(__half2*)&p.y);
            a0 = fmaf(w, lo.x, a0); a1 = fmaf(w, lo.y, a1);
            a2 = fmaf(w, hi.x, a2); a3 = fmaf(w, hi.y, a3);
        }
    }

    float rinv = 1.0f / den;
    float4 b4 = *(const float4*)(bias + lane * 4);
    float y0 = fmaf(a0, rinv, b4.x), y1 = fmaf(a1, rinv, b4.y);
    float y2 = fmaf(a2, rinv, b4.z), y3 = fmaf(a3, rinv, b4.w);
    *(float4*)(out + (size_t)n * FOUT + lane * 4) = make_float4(y0, y1, y2, y3);

    int c = lane * 4;
    atomicAdd(&s_acc[c + 0], y0); atomicAdd(&s_acc[128 + c + 0], y0 * y0);
    atomicAdd(&s_acc[c + 1], y1); atomicAdd(&s_acc[128 + c + 1], y1 * y1);
    atomicAdd(&s_acc[c + 2], y2); atomicAdd(&s_acc[128 + c + 2], y2 * y2);
    atomicAdd(&s_acc[c + 3], y3); atomicAdd(&s_acc[128 + c + 3], y3 * y3);
    __syncthreads();
    atomicAdd(&g_stats[threadIdx.x], s_acc[threadIdx.x]);
}

// ---------------------------------------------------------------------------
// Kernel 6: finalize — BN + LeakyReLU(0.01), float4 in place.
// Also re-zeroes g_deg for the NEXT invocation (g_off fully consumed by now).
// ---------------------------------------------------------------------------
__global__ __launch_bounds__(256) void final_k(float* __restrict__ out,
                                               const float* __restrict__ gamma,
                                               const float* __restrict__ beta) {
    size_t idx = (size_t)blockIdx.x * blockDim.x + threadIdx.x;     // over N*32
    if (idx < NN) g_deg[idx] = 0;
    if (idx >= (size_t)NN * 32) return;
    int c = (int)(idx & 31) * 4;
    size_t r = idx >> 5;

    float4 v = *(float4*)(out + r * FOUT + c);
    const float invN = 1.0f / NN;
    float y[4] = {v.x, v.y, v.z, v.w};
#pragma unroll
    for (int j = 0; j < 4; j++) {
        int cc = c + j;
        float mu  = g_stats[cc] * invN;
        float var = fmaf(g_stats[128 + cc], invN, -mu * mu);
        float zz = (y[j] - mu) * rsqrtf(var + BN_EPS) * gamma[cc] + beta[cc];
        y[j] = zz < 0.f ? NEG_ACT * zz : zz;
    }
    *(float4*)(out + r * FOUT + c) = make_float4(y[0], y[1], y[2], y[3]);
}

// ---------------------------------------------------------------------------
// Launch: CSR build (depends only on edge_idx) forked onto a second stream,
// overlapping the GEMM. Event fork/join keeps the captured graph correct.
// ---------------------------------------------------------------------------
extern "C" void kernel_launch(void* const* d_in, const int* in_sizes, int n_in,
                              void* d_out, int out_size) {
    const float* x       = (const float*)d_in[0];
    const int*   ei      = (const int*)  d_in[1];
    const float* W       = (const float*)d_in[2];
    const float* att_src = (const float*)d_in[3];
    const float* att_dst = (const float*)d_in[4];
    const float* bias    = (const float*)d_in[5];
    const float* gamma   = (const float*)d_in[6];
    const float* beta    = (const float*)d_in[7];
    float* out = (float*)d_out;

    static cudaStream_t s2 = nullptr;
    static cudaEvent_t  eFork = nullptr, eJoin = nullptr;
    if (!s2) {
        cudaStreamCreateWithFlags(&s2, cudaStreamNonBlocking);
        cudaEventCreateWithFlags(&eFork, cudaEventDisableTiming);
        cudaEventCreateWithFlags(&eJoin, cudaEventDisableTiming);
    }

    // fork CSR-build branch
    cudaEventRecord(eFork, 0);
    cudaStreamWaitEvent(s2, eFork, 0);
    hist_k    <<<(EE + 255) / 256, 256, 0, s2>>>(ei);
    blocksum_k<<<NB, 256, 0, s2>>>();
    scanblk_k <<<1, 256, 0, s2>>>();
    offsets_k <<<NB, 256, 0, s2>>>();
    scatter_k <<<(EE + 255) / 256, 256, 0, s2>>>(ei);
    cudaEventRecord(eJoin, s2);

    // main branch (concurrent with CSR build)
    gemm_tc<<<(NN + 127) / 128, 256>>>(x, W, att_src, att_dst);

    // join, then aggregate + finalize
    cudaStreamWaitEvent(0, eJoin, 0);
    agg_k  <<<NN / 8, 256>>>(bias, out);
    final_k<<<(int)(((size_t)NN * 32 + 255) / 256), 256>>>(out, gamma, beta);
}